// round 11
// baseline (speedup 1.0000x reference)
#include <cuda_runtime.h>

namespace {

constexpr int NBATCH = 256;
constexpr int NTIME  = 512;
constexpr int TPB    = 128;
constexpr float DT_STEP = 0.01f;

// XLA / Eigen f32 tanh rational approximation (bit-matches XLA's EmitTanh).
__device__ __forceinline__ float xla_tanh(float x) {
  const float CL = 7.90531110763549805f;
  float xc = fmaxf(fminf(x, CL), -CL);
  float x2 = __fmul_rn(xc, xc);
  float p = fmaf(x2, -2.76076847742355e-16f, 2.00018790482477e-13f);
  p = fmaf(x2, p, -8.60467152213735e-11f);
  p = fmaf(x2, p, 5.12229709037114e-08f);
  p = fmaf(x2, p, 1.48572235717979e-05f);
  p = fmaf(x2, p, 6.37261928875436e-04f);
  p = fmaf(x2, p, 4.89352455891786e-03f);
  p = __fmul_rn(xc, p);
  float q = fmaf(x2, 1.19825839466702e-06f, 1.18534705686654e-04f);
  q = fmaf(x2, q, 2.26843463243900e-03f);
  q = fmaf(x2, q, 4.89352518554385e-03f);
  float r = __fdiv_rn(p, q);
  return (fabsf(x) < 0.0004f) ? x : r;
}

// JAX tanh JVP (g + g*ans)*(1-ans), FFMA-contracted then FMUL.
__device__ __forceinline__ float tanh_jvp(float t, float a, float om) {
  return __fmul_rn(fmaf(t, a, t), om);
}

// NEON-style pairwise combine of 4 partial sums: (s0+s1)+(s2+s3)
__device__ __forceinline__ float comb4(const float* s) {
  return __fadd_rn(__fadd_rn(s[0], s[1]), __fadd_rn(s[2], s[3]));
}

// 4-lane interleaved f32 dot: lane j takes k = j, j+4, ...  (K multiple of 4)
template<int K>
__device__ __forceinline__ float dot4(const float* __restrict__ a,
                                      const float* __restrict__ w,
                                      int stride, int c) {
  float s[4] = {0.f, 0.f, 0.f, 0.f};
#pragma unroll
  for (int k = 0; k < K; k += 4) {
#pragma unroll
    for (int l = 0; l < 4; ++l)
      s[l] = fmaf(a[k + l], w[(k + l) * stride + c], s[l]);
  }
  return comb4(s);
}

struct Smem {
  // ---- weights ----
  float W0[1024]; float b0[64];     // dyn layer0: 16x64
  float W1[4096]; float b1[64];     // dyn layer1: 64x64
  float W2[2048]; float b2[32];     // dyn layer2: 64x32
  float W3[384];  float b3[12];     // dyn layer3: 32x12
  float mW0[768]; float mb0[64];    // meas layer0: 12x64
  float mW1[4096]; float mb1[64];   // meas layer1: 64x64
  float mW2[576]; float mb2[12];    // meas layer2: 64x9
  float Qm[144];  float Rm[82];
  // ---- scratch ----
  float Ta[768], Tb[768];
  float a1[64], om1[64], a2[64], om2[64], a3[32], om3[32];
  float m1[64], mg1[64], m2[64], mg2[64];
  float x[12], xp[12], u[4], z[10], zp[10];
  float P[144], Pp[144], F[144], FP[144];
  float H[108], HP[108], PHt[108];
  float Mf[190];                    // 9 x 21 augmented [S | PHt^T]
  float Kt[108];                    // X = S^{-1} PHt^T  (9 x 12), K = X^T
};

// O[12][64] = epilogue( A[12][64] @ W[64][64] ), 4-lane interleaved f32.
template<bool TANH>
__device__ __forceinline__ void mm12x64(const float* __restrict__ A,
                                        const float* __restrict__ W,
                                        const float* __restrict__ act,
                                        const float* __restrict__ omk,
                                        float* __restrict__ O, int tid) {
  const int cg = tid & 31;
  const int jg = tid >> 5;          // warp-uniform -> broadcast A reads
  const int c0 = cg << 1;
  const float* a0 = A + (jg * 3 + 0) * 64;
  const float* a1p = A + (jg * 3 + 1) * 64;
  const float* a2p = A + (jg * 3 + 2) * 64;
  float acc[6][4];
#pragma unroll
  for (int o = 0; o < 6; ++o)
#pragma unroll
    for (int l = 0; l < 4; ++l) acc[o][l] = 0.f;
#pragma unroll 4
  for (int k = 0; k < 64; k += 4) {
#pragma unroll
    for (int l = 0; l < 4; ++l) {
      float2 w = *reinterpret_cast<const float2*>(W + (k + l) * 64 + c0);
      float v0 = a0[k + l], v1 = a1p[k + l], v2 = a2p[k + l];
      acc[0][l] = fmaf(v0, w.x, acc[0][l]); acc[1][l] = fmaf(v0, w.y, acc[1][l]);
      acc[2][l] = fmaf(v1, w.x, acc[2][l]); acc[3][l] = fmaf(v1, w.y, acc[3][l]);
      acc[4][l] = fmaf(v2, w.x, acc[4][l]); acc[5][l] = fmaf(v2, w.y, acc[5][l]);
    }
  }
  float f[6];
#pragma unroll
  for (int o = 0; o < 6; ++o) f[o] = comb4(acc[o]);
  if (TANH) {
    const float ax = act[c0], ay = act[c0 + 1];
    const float ox = omk[c0], oy = omk[c0 + 1];
    O[(jg * 3 + 0) * 64 + c0]     = tanh_jvp(f[0], ax, ox);
    O[(jg * 3 + 0) * 64 + c0 + 1] = tanh_jvp(f[1], ay, oy);
    O[(jg * 3 + 1) * 64 + c0]     = tanh_jvp(f[2], ax, ox);
    O[(jg * 3 + 1) * 64 + c0 + 1] = tanh_jvp(f[3], ay, oy);
    O[(jg * 3 + 2) * 64 + c0]     = tanh_jvp(f[4], ax, ox);
    O[(jg * 3 + 2) * 64 + c0 + 1] = tanh_jvp(f[5], ay, oy);
  } else {
    const bool mx = omk[c0] != 0.f, my = omk[c0 + 1] != 0.f;
    O[(jg * 3 + 0) * 64 + c0]     = mx ? f[0] : 0.f;
    O[(jg * 3 + 0) * 64 + c0 + 1] = my ? f[1] : 0.f;
    O[(jg * 3 + 1) * 64 + c0]     = mx ? f[2] : 0.f;
    O[(jg * 3 + 1) * 64 + c0 + 1] = my ? f[3] : 0.f;
    O[(jg * 3 + 2) * 64 + c0]     = mx ? f[4] : 0.f;
    O[(jg * 3 + 2) * 64 + c0 + 1] = my ? f[5] : 0.f;
  }
}

// fp32 LAPACK sgetf2 (partial pivot, reciprocal scaling) + sgetrs on [S|PHt^T].
__device__ __forceinline__ void lu_solve_warp(const float* __restrict__ Mf,
                                              float* __restrict__ Kt, int lane) {
  const unsigned FULL = 0xffffffffu;
  float r[21];
#pragma unroll
  for (int j = 0; j < 21; ++j) r[j] = (lane < 9) ? Mf[lane * 21 + j] : 0.f;
#pragma unroll
  for (int k = 0; k < 9; ++k) {
    float key = (lane >= k && lane < 9) ? fabsf(r[k]) : -1.0f;
    int idx = lane;
#pragma unroll
    for (int off = 16; off > 0; off >>= 1) {
      float ok = __shfl_xor_sync(FULL, key, off);
      int oi = __shfl_xor_sync(FULL, idx, off);
      if (ok > key || (ok == key && oi < idx)) { key = ok; idx = oi; }
    }
    int p = idx;
    int partner = (lane == k) ? p : ((lane == p) ? k : lane);
#pragma unroll
    for (int j = 0; j < 21; ++j) r[j] = __shfl_sync(FULL, r[j], partner);
    float piv = __shfl_sync(FULL, r[k], k);
    float rcp = __fdiv_rn(1.0f, piv);
    float rk[21];
#pragma unroll
    for (int j = 0; j < 21; ++j) rk[j] = __shfl_sync(FULL, r[j], k);
    if (lane > k && lane < 9) {
      float l = __fmul_rn(r[k], rcp);
      r[k] = l;
#pragma unroll
      for (int j = 0; j < 21; ++j)
        if (j > k) r[j] = fmaf(l, -rk[j], r[j]);
    }
  }
#pragma unroll
  for (int k = 8; k >= 0; --k) {
    if (lane == k) {
#pragma unroll
      for (int c = 9; c < 21; ++c) r[c] = __fdiv_rn(r[c], r[k]);
    }
#pragma unroll
    for (int c = 9; c < 21; ++c) {
      float xv = __shfl_sync(FULL, r[c], k);
      if (lane < k) r[c] = fmaf(r[k], -xv, r[c]);
    }
  }
  if (lane < 9) {
#pragma unroll
    for (int c = 0; c < 12; ++c) Kt[lane * 12 + c] = r[9 + c];
  }
}

// predict: consumes s.x, s.P, s.u -> produces s.xp, s.Pp
__device__ __forceinline__ void do_predict(Smem& s, int tid) {
  // D1: dyn layer0 forward (K=16 over concat(x,u), 4-lane interleaved)
  if (tid < 64) {
    float sv[4] = {0.f, 0.f, 0.f, 0.f};
#pragma unroll
    for (int k = 0; k < 12; k += 4)
#pragma unroll
      for (int l = 0; l < 4; ++l)
        sv[l] = fmaf(s.x[k + l], s.W0[(k + l) * 64 + tid], sv[l]);
#pragma unroll
    for (int l = 0; l < 4; ++l)
      sv[l] = fmaf(s.u[l], s.W0[(12 + l) * 64 + tid], sv[l]);
    float a = xla_tanh(__fadd_rn(comb4(sv), s.b0[tid]));
    s.a1[tid] = a;
    s.om1[tid] = __fsub_rn(1.f, a);
  }
  __syncthreads();
  // D2: layer1 forward (64 thr, K=64 4-lane) + T1 = jvp(W0[:12] rows)
  if (tid < 64) {
    float d = dot4<64>(s.a1, s.W1, 64, tid);
    float a = xla_tanh(__fadd_rn(d, s.b1[tid]));
    s.a2[tid] = a;
    s.om2[tid] = __fsub_rn(1.f, a);
  } else {
    for (int idx = tid - 64; idx < 768; idx += 64) {
      int c = idx & 63;
      s.Ta[idx] = tanh_jvp(s.W0[idx], s.a1[c], s.om1[c]);
    }
  }
  __syncthreads();
  // D3: T2 = jvp(T1 @ W1)  (4-lane)
  mm12x64<true>(s.Ta, s.W1, s.a2, s.om2, s.Tb, tid);
  __syncthreads();
  // D4: layer2 forward (32 thr) + raw T3 = T2 @ W2 (96 thr) -- 4-lane K=64
  if (tid < 32) {
    float d = dot4<64>(s.a2, s.W2, 32, tid);
    float a = xla_tanh(__fadd_rn(d, s.b2[tid]));
    s.a3[tid] = a;
    s.om3[tid] = __fsub_rn(1.f, a);
  } else {
    for (int idx = tid - 32; idx < 384; idx += 96) {
      int j = idx >> 5, c = idx & 31;
      s.Ta[j * 32 + c] = dot4<64>(s.Tb + j * 64, s.W2, 32, c);  // raw T3
    }
  }
  __syncthreads();
  // D5: residual + xp (12 thr) + F (all 128) -- K=32 4-lane
  if (tid < 12) {
    const int i = tid;
    float d = dot4<32>(s.a3, s.W3, 12, i);
    float drift = 0.f;
    if (i < 3) drift = s.x[i + 3];
    else if (i >= 6 && i < 9) drift = s.x[i + 3];
    float base = fmaf(DT_STEP, drift, s.x[i]);
    s.xp[i] = __fadd_rn(base, __fadd_rn(d, s.b3[i]));
  }
  for (int idx = tid; idx < 144; idx += TPB) {
    int i = idx / 12, j = idx % 12;
    const float* tr = s.Ta + j * 32;
    float sv[4] = {0.f, 0.f, 0.f, 0.f};
#pragma unroll
    for (int k = 0; k < 32; k += 4)
#pragma unroll
      for (int l = 0; l < 4; ++l) {
        float t3 = tanh_jvp(tr[k + l], s.a3[k + l], s.om3[k + l]);
        sv[l] = fmaf(t3, s.W3[(k + l) * 12 + i], sv[l]);
      }
    float acc = comb4(sv);
    float base = 0.f;
    if (i == j) base = 1.f;
    else if ((i < 3 || (i >= 6 && i < 9)) && j == i + 3) base = DT_STEP;
    s.F[idx] = __fadd_rn(acc, base);
  }
  __syncthreads();
  // D6: FP = F @ P  (tiny algebra: matched sequential f32)
  for (int idx = tid; idx < 144; idx += TPB) {
    int i = idx / 12, j = idx % 12;
    float acc = 0.f;
#pragma unroll
    for (int k = 0; k < 12; ++k) acc = fmaf(s.F[i * 12 + k], s.P[k * 12 + j], acc);
    s.FP[idx] = acc;
  }
  __syncthreads();
  // D7: Pp = (FP @ F^T) + Q
  for (int idx = tid; idx < 144; idx += TPB) {
    int i = idx / 12, j = idx % 12;
    float acc = 0.f;
#pragma unroll
    for (int k = 0; k < 12; ++k) acc = fmaf(s.FP[i * 12 + k], s.F[j * 12 + k], acc);
    s.Pp[idx] = __fadd_rn(acc, s.Qm[idx]);
  }
  __syncthreads();
}

// update: consumes s.xp, s.Pp, s.z -> produces s.x, s.P, s.zp
__device__ __forceinline__ void do_update(Smem& s, int tid) {
  // M1: meas layer0 forward (relu) -- K=12, exact fp64 (as R10)
  if (tid < 64) {
    double acc = 0.;
#pragma unroll
    for (int k = 0; k < 12; ++k) acc = fma((double)s.xp[k], (double)s.mW0[k * 64 + tid], acc);
    float pre = __fadd_rn((float)acc, s.mb0[tid]);
    s.m1[tid] = fmaxf(pre, 0.f);
    s.mg1[tid] = pre > 0.f ? 1.f : 0.f;
  }
  __syncthreads();
  // M2: meas layer1 forward (64 thr, K=64 4-lane) + mT1 select (64 thr)
  if (tid < 64) {
    float d = dot4<64>(s.m1, s.mW1, 64, tid);
    float pre = __fadd_rn(d, s.mb1[tid]);
    s.m2[tid] = fmaxf(pre, 0.f);
    s.mg2[tid] = pre > 0.f ? 1.f : 0.f;
  } else {
    for (int idx = tid - 64; idx < 768; idx += 64) {
      int c = idx & 63;
      s.Ta[idx] = s.mg1[c] != 0.f ? s.mW0[idx] : 0.f;
    }
  }
  __syncthreads();
  // U1: mT2 = select(mT1 @ mW1)  (4-lane)
  mm12x64<false>(s.Ta, s.mW1, s.m2, s.mg2, s.Tb, tid);
  __syncthreads();
  // U2: H (108 thr) + z_pred (9 thr) -- K=64 4-lane
  if (tid < 108) {
    int i = tid / 12, j = tid % 12;
    float f = dot4<64>(s.Tb + j * 64, s.mW2, 9, i);
    s.H[tid] = (i == j) ? __fadd_rn(f, 1.f) : f;
  } else if (tid < 117) {
    int i = tid - 108;
    float f = dot4<64>(s.m2, s.mW2, 9, i);
    s.zp[i] = __fadd_rn(s.xp[i], __fadd_rn(f, s.mb2[i]));
  }
  __syncthreads();
  // U3: HP = H @ Pp  and  PHt = Pp @ H^T  (matched sequential f32)
  for (int idx = tid; idx < 216; idx += TPB) {
    if (idx < 108) {
      int i = idx / 12, j = idx % 12;
      float acc = 0.f;
#pragma unroll
      for (int k = 0; k < 12; ++k) acc = fmaf(s.H[i * 12 + k], s.Pp[k * 12 + j], acc);
      s.HP[idx] = acc;
    } else {
      int r = idx - 108;
      int i = r / 9, j = r % 9;
      float acc = 0.f;
#pragma unroll
      for (int k = 0; k < 12; ++k) acc = fmaf(s.Pp[i * 12 + k], s.H[j * 12 + k], acc);
      s.PHt[i * 9 + j] = acc;
    }
  }
  __syncthreads();
  // U4: augmented Mf = [S | PHt^T],  S = (HP @ H^T) + R  (matched f32)
  for (int idx = tid; idx < 189; idx += TPB) {
    int i = idx / 21, c = idx % 21;
    float v;
    if (c < 9) {
      float acc = 0.f;
#pragma unroll
      for (int k = 0; k < 12; ++k) acc = fmaf(s.HP[i * 12 + k], s.H[c * 12 + k], acc);
      v = __fadd_rn(acc, s.Rm[i * 9 + c]);
    } else {
      v = s.PHt[(c - 9) * 9 + i];
    }
    s.Mf[idx] = v;
  }
  __syncthreads();
  // fp32 LAPACK-style LU solve (warp 0)
  if (tid < 32) lu_solve_warp(s.Mf, s.Kt, tid);
  __syncthreads();
  // U5: x_new = xp + K @ (z - zp);  E = I - K @ H  (matched f32)
  if (tid < 12) {
    const int i = tid;
    float acc = 0.f;
#pragma unroll
    for (int k = 0; k < 9; ++k)
      acc = fmaf(s.Kt[k * 12 + i], __fsub_rn(s.z[k], s.zp[k]), acc);
    s.x[i] = __fadd_rn(s.xp[i], acc);
  }
  for (int idx = tid; idx < 144; idx += TPB) {
    int i = idx / 12, j = idx % 12;
    float acc = 0.f;
#pragma unroll
    for (int k = 0; k < 9; ++k)
      acc = fmaf(s.Kt[k * 12 + i], s.H[k * 12 + j], acc);
    s.FP[idx] = __fsub_rn((i == j) ? 1.f : 0.f, acc);
  }
  __syncthreads();
  // U6: P = E @ Pp  (matched f32)
  for (int idx = tid; idx < 144; idx += TPB) {
    int i = idx / 12, j = idx % 12;
    float acc = 0.f;
#pragma unroll
    for (int k = 0; k < 12; ++k)
      acc = fmaf(s.FP[i * 12 + k], s.Pp[k * 12 + j], acc);
    s.P[idx] = acc;
  }
  __syncthreads();
}

} // namespace

__global__ __launch_bounds__(TPB) void ekf_kernel(
    const float* __restrict__ controls,
    const float* __restrict__ measurements,
    const float* __restrict__ init_x,
    const float* __restrict__ init_P,
    const float* __restrict__ Qg,
    const float* __restrict__ Rg,
    const float* __restrict__ dW0, const float* __restrict__ db0,
    const float* __restrict__ dW1, const float* __restrict__ db1,
    const float* __restrict__ dW2, const float* __restrict__ db2,
    const float* __restrict__ dW3, const float* __restrict__ db3,
    const float* __restrict__ mW0p, const float* __restrict__ mb0p,
    const float* __restrict__ mW1p, const float* __restrict__ mb1p,
    const float* __restrict__ mW2p, const float* __restrict__ mb2p,
    float* __restrict__ out)
{
  extern __shared__ float smraw[];
  Smem& s = *reinterpret_cast<Smem*>(smraw);
  const int tid = threadIdx.x;
  const int b = blockIdx.x;

#define CPY(dst, src, n)  for (int i_ = tid; i_ < (n); i_ += TPB) (dst)[i_] = (src)[i_]
  CPY(s.W0, dW0, 1024); CPY(s.b0, db0, 64);
  CPY(s.W1, dW1, 4096); CPY(s.b1, db1, 64);
  CPY(s.W2, dW2, 2048); CPY(s.b2, db2, 32);
  CPY(s.W3, dW3, 384);  CPY(s.b3, db3, 12);
  CPY(s.mW0, mW0p, 768);  CPY(s.mb0, mb0p, 64);
  CPY(s.mW1, mW1p, 4096); CPY(s.mb1, mb1p, 64);
  CPY(s.mW2, mW2p, 576);  CPY(s.mb2, mb2p, 9);
  CPY(s.Qm, Qg, 144);
  CPY(s.Rm, Rg, 81);
#undef CPY
  if (tid < 12) s.xp[tid] = init_x[b * 12 + tid];
  for (int i = tid; i < 144; i += TPB) s.Pp[i] = init_P[b * 144 + i];
  if (tid >= 16 && tid < 25) s.z[tid - 16] = measurements[((size_t)b * NTIME + 0) * 9 + (tid - 16)];
  __syncthreads();

  float* est = out;
  float* pm  = out + (size_t)NBATCH * NTIME * 12;
  float* cv  = out + (size_t)NBATCH * NTIME * 21;

  // t = 0: measurement update only
  do_update(s, tid);
  {
    if (tid < 12) est[((size_t)b * NTIME + 0) * 12 + tid] = s.x[tid];
    if (tid >= 32 && tid < 41) pm[((size_t)b * NTIME + 0) * 9 + (tid - 32)] = s.zp[tid - 32];
    for (int i = tid; i < 144; i += TPB) cv[((size_t)b * NTIME + 0) * 144 + i] = s.P[i];
    if (tid >= 64 && tid < 68) s.u[tid - 64] = controls[((size_t)b * NTIME + 1) * 4 + (tid - 64)];
    if (tid >= 80 && tid < 89) s.z[tid - 80] = measurements[((size_t)b * NTIME + 1) * 9 + (tid - 80)];
  }
  __syncthreads();

  for (int t = 1; t < NTIME; ++t) {
    do_predict(s, tid);
    do_update(s, tid);
    if (tid < 12) est[((size_t)b * NTIME + t) * 12 + tid] = s.x[tid];
    if (tid >= 32 && tid < 41) pm[((size_t)b * NTIME + t) * 9 + (tid - 32)] = s.zp[tid - 32];
    for (int i = tid; i < 144; i += TPB) cv[((size_t)b * NTIME + t) * 144 + i] = s.P[i];
    if (t + 1 < NTIME) {
      if (tid >= 64 && tid < 68) s.u[tid - 64] = controls[((size_t)b * NTIME + t + 1) * 4 + (tid - 64)];
      if (tid >= 80 && tid < 89) s.z[tid - 80] = measurements[((size_t)b * NTIME + t + 1) * 9 + (tid - 80)];
    }
    __syncthreads();
  }
}

extern "C" void kernel_launch(void* const* d_in, const int* in_sizes, int n_in,
                              void* d_out, int out_size) {
  // inputs: 0 states (unused), 1 controls, 2 measurements, 3 initial_state,
  // 4 initial_covariance, 5 Q, 6 R, 7..14 dW/db 0..3, 15..20 mW/mb 0..2
  const float* controls = (const float*)d_in[1];
  const float* meas     = (const float*)d_in[2];
  const float* x0       = (const float*)d_in[3];
  const float* P0       = (const float*)d_in[4];
  const float* Qg       = (const float*)d_in[5];
  const float* Rg       = (const float*)d_in[6];
  const float* dW0 = (const float*)d_in[7];
  const float* db0 = (const float*)d_in[8];
  const float* dW1 = (const float*)d_in[9];
  const float* db1 = (const float*)d_in[10];
  const float* dW2 = (const float*)d_in[11];
  const float* db2 = (const float*)d_in[12];
  const float* dW3 = (const float*)d_in[13];
  const float* db3 = (const float*)d_in[14];
  const float* mW0 = (const float*)d_in[15];
  const float* mb0 = (const float*)d_in[16];
  const float* mW1 = (const float*)d_in[17];
  const float* mb1 = (const float*)d_in[18];
  const float* mW2 = (const float*)d_in[19];
  const float* mb2 = (const float*)d_in[20];
  float* out = (float*)d_out;

  int smem = (int)sizeof(Smem);
  cudaFuncSetAttribute(ekf_kernel, cudaFuncAttributeMaxDynamicSharedMemorySize, smem);
  ekf_kernel<<<NBATCH, TPB, smem>>>(controls, meas, x0, P0, Qg, Rg,
                                    dW0, db0, dW1, db1, dW2, db2, dW3, db3,
                                    mW0, mb0, mW1, mb1, mW2, mb2, out);
}

// round 12
// speedup vs baseline: 1.0005x; 1.0005x over previous
#include <cuda_runtime.h>

namespace {

constexpr int NBATCH = 256;
constexpr int NTIME  = 512;
constexpr int TPB    = 128;
constexpr float DT_STEP = 0.01f;

// XLA / Eigen f32 tanh rational approximation (bit-matches XLA's EmitTanh).
__device__ __forceinline__ float xla_tanh(float x) {
  const float CL = 7.90531110763549805f;
  float xc = fmaxf(fminf(x, CL), -CL);
  float x2 = __fmul_rn(xc, xc);
  float p = fmaf(x2, -2.76076847742355e-16f, 2.00018790482477e-13f);
  p = fmaf(x2, p, -8.60467152213735e-11f);
  p = fmaf(x2, p, 5.12229709037114e-08f);
  p = fmaf(x2, p, 1.48572235717979e-05f);
  p = fmaf(x2, p, 6.37261928875436e-04f);
  p = fmaf(x2, p, 4.89352455891786e-03f);
  p = __fmul_rn(xc, p);
  float q = fmaf(x2, 1.19825839466702e-06f, 1.18534705686654e-04f);
  q = fmaf(x2, q, 2.26843463243900e-03f);
  q = fmaf(x2, q, 4.89352518554385e-03f);
  float r = __fdiv_rn(p, q);
  return (fabsf(x) < 0.0004f) ? x : r;
}

// JAX tanh JVP (g + g*ans)*(1-ans), FFMA-contracted then FMUL.
__device__ __forceinline__ float tanh_jvp(float t, float a, float om) {
  return __fmul_rn(fmaf(t, a, t), om);
}

// NEON-style pairwise combine of 4 partial sums: (s0+s1)+(s2+s3)
__device__ __forceinline__ float comb4(const float* s) {
  return __fadd_rn(__fadd_rn(s[0], s[1]), __fadd_rn(s[2], s[3]));
}

__device__ __forceinline__ void barsync(int id, int cnt) {
  asm volatile("bar.sync %0, %1;" :: "r"(id), "r"(cnt) : "memory");
}
__device__ __forceinline__ void bararrive(int id, int cnt) {
  asm volatile("bar.arrive %0, %1;" :: "r"(id), "r"(cnt) : "memory");
}

// 4-lane interleaved f32 dot, float4 a-loads (identical FMA order to scalar).
template<int K>
__device__ __forceinline__ float dot4(const float* __restrict__ a,
                                      const float* __restrict__ w,
                                      int stride, int c) {
  float s0 = 0.f, s1 = 0.f, s2 = 0.f, s3 = 0.f;
#pragma unroll
  for (int k = 0; k < K; k += 4) {
    float4 av = *reinterpret_cast<const float4*>(a + k);
    s0 = fmaf(av.x, w[k * stride + c], s0);
    s1 = fmaf(av.y, w[(k + 1) * stride + c], s1);
    s2 = fmaf(av.z, w[(k + 2) * stride + c], s2);
    s3 = fmaf(av.w, w[(k + 3) * stride + c], s3);
  }
  float sv[4] = {s0, s1, s2, s3};
  return comb4(sv);
}

struct Smem {
  // ---- weights (all array sizes multiples of 4 floats -> 16B alignment) ----
  float W0[1024]; float b0[64];
  float W1[4096]; float b1[64];
  float W2[2048]; float b2[32];
  float W3[384];  float b3[12];
  float mW0[768]; float mb0[64];
  float mW1[4096]; float mb1[64];
  float mW2[576]; float mb2[12];
  float Qm[144];  float Rm[84];
  // ---- scratch ----
  float Ta[768], Tb[768];
  float a1[64], om1[64], a2[64], om2[64], a3[32], om3[32];
  float m1[64], mg1[64], m2[64], mg2[64];
  float x[12], xp[12], u[4], z[12], zp[12];
  float P[144], Pp[144], F[144], FP[144];
  float H[108], HP[108];
  float Mf[192];                    // 9 x 21 augmented [S | PHt^T]
  float Kt[108];
};

// O[12][64] = epilogue( A[12][64] @ W[64][64] ), 4-lane, float4 a-loads.
template<bool TANH>
__device__ __forceinline__ void mm12x64(const float* __restrict__ A,
                                        const float* __restrict__ W,
                                        const float* __restrict__ act,
                                        const float* __restrict__ omk,
                                        float* __restrict__ O, int tid) {
  const int cg = tid & 31;
  const int jg = tid >> 5;
  const int c0 = cg << 1;
  const float* a0 = A + (jg * 3 + 0) * 64;
  const float* a1p = A + (jg * 3 + 1) * 64;
  const float* a2p = A + (jg * 3 + 2) * 64;
  float acc[6][4];
#pragma unroll
  for (int o = 0; o < 6; ++o)
#pragma unroll
    for (int l = 0; l < 4; ++l) acc[o][l] = 0.f;
#pragma unroll 4
  for (int k = 0; k < 64; k += 4) {
    float A0[4], A1[4], A2[4];
    *reinterpret_cast<float4*>(A0) = *reinterpret_cast<const float4*>(a0 + k);
    *reinterpret_cast<float4*>(A1) = *reinterpret_cast<const float4*>(a1p + k);
    *reinterpret_cast<float4*>(A2) = *reinterpret_cast<const float4*>(a2p + k);
#pragma unroll
    for (int l = 0; l < 4; ++l) {
      float2 w = *reinterpret_cast<const float2*>(W + (k + l) * 64 + c0);
      acc[0][l] = fmaf(A0[l], w.x, acc[0][l]); acc[1][l] = fmaf(A0[l], w.y, acc[1][l]);
      acc[2][l] = fmaf(A1[l], w.x, acc[2][l]); acc[3][l] = fmaf(A1[l], w.y, acc[3][l]);
      acc[4][l] = fmaf(A2[l], w.x, acc[4][l]); acc[5][l] = fmaf(A2[l], w.y, acc[5][l]);
    }
  }
  float f[6];
#pragma unroll
  for (int o = 0; o < 6; ++o) f[o] = comb4(acc[o]);
  if (TANH) {
    const float ax = act[c0], ay = act[c0 + 1];
    const float ox = omk[c0], oy = omk[c0 + 1];
    O[(jg * 3 + 0) * 64 + c0]     = tanh_jvp(f[0], ax, ox);
    O[(jg * 3 + 0) * 64 + c0 + 1] = tanh_jvp(f[1], ay, oy);
    O[(jg * 3 + 1) * 64 + c0]     = tanh_jvp(f[2], ax, ox);
    O[(jg * 3 + 1) * 64 + c0 + 1] = tanh_jvp(f[3], ay, oy);
    O[(jg * 3 + 2) * 64 + c0]     = tanh_jvp(f[4], ax, ox);
    O[(jg * 3 + 2) * 64 + c0 + 1] = tanh_jvp(f[5], ay, oy);
  } else {
    const bool mx = omk[c0] != 0.f, my = omk[c0 + 1] != 0.f;
    O[(jg * 3 + 0) * 64 + c0]     = mx ? f[0] : 0.f;
    O[(jg * 3 + 0) * 64 + c0 + 1] = my ? f[1] : 0.f;
    O[(jg * 3 + 1) * 64 + c0]     = mx ? f[2] : 0.f;
    O[(jg * 3 + 1) * 64 + c0 + 1] = my ? f[3] : 0.f;
    O[(jg * 3 + 2) * 64 + c0]     = mx ? f[4] : 0.f;
    O[(jg * 3 + 2) * 64 + c0 + 1] = my ? f[5] : 0.f;
  }
}

// fp32 LAPACK sgetf2 (partial pivot, reciprocal scaling) + sgetrs on [S|PHt^T].
__device__ __forceinline__ void lu_solve_warp(const float* __restrict__ Mf,
                                              float* __restrict__ Kt, int lane) {
  const unsigned FULL = 0xffffffffu;
  float r[21];
#pragma unroll
  for (int j = 0; j < 21; ++j) r[j] = (lane < 9) ? Mf[lane * 21 + j] : 0.f;
#pragma unroll
  for (int k = 0; k < 9; ++k) {
    float key = (lane >= k && lane < 9) ? fabsf(r[k]) : -1.0f;
    int idx = lane;
#pragma unroll
    for (int off = 8; off > 0; off >>= 1) {   // lanes 0..15 fully reduce
      float ok = __shfl_xor_sync(FULL, key, off);
      int oi = __shfl_xor_sync(FULL, idx, off);
      if (ok > key || (ok == key && oi < idx)) { key = ok; idx = oi; }
    }
    int p = idx;
    int partner = (lane == k) ? p : ((lane == p) ? k : lane);
#pragma unroll
    for (int j = 0; j < 21; ++j) r[j] = __shfl_sync(FULL, r[j], partner);
    float piv = __shfl_sync(FULL, r[k], k);
    float rcp = __fdiv_rn(1.0f, piv);
    float rk[21];
#pragma unroll
    for (int j = 0; j < 21; ++j) rk[j] = __shfl_sync(FULL, r[j], k);
    if (lane > k && lane < 9) {
      float l = __fmul_rn(r[k], rcp);
      r[k] = l;
#pragma unroll
      for (int j = 0; j < 21; ++j)
        if (j > k) r[j] = fmaf(l, -rk[j], r[j]);
    }
  }
#pragma unroll
  for (int k = 8; k >= 0; --k) {
    if (lane == k) {
#pragma unroll
      for (int c = 9; c < 21; ++c) r[c] = __fdiv_rn(r[c], r[k]);
    }
#pragma unroll
    for (int c = 9; c < 21; ++c) {
      float xv = __shfl_sync(FULL, r[c], k);
      if (lane < k) r[c] = fmaf(r[k], -xv, r[c]);
    }
  }
  if (lane < 9) {
#pragma unroll
    for (int c = 0; c < 12; ++c) Kt[lane * 12 + c] = r[9 + c];
  }
}

// predict: consumes s.x, s.P, s.u -> produces s.xp, s.F (D6/D7 moved to update)
// W23 in phase 1 stores the PREVIOUS step's outputs (e, pmo, c).
__device__ __forceinline__ void do_predict(Smem& s, int tid,
                                           float* __restrict__ e,
                                           float* __restrict__ pmo,
                                           float* __restrict__ c) {
  // P1: D1 forward (W01) | previous-step stores (W23)
  if (tid < 64) {
    float s0 = 0.f, s1 = 0.f, s2 = 0.f, s3 = 0.f;
#pragma unroll
    for (int k = 0; k < 12; k += 4) {
      float4 xv = *reinterpret_cast<const float4*>(s.x + k);
      s0 = fmaf(xv.x, s.W0[k * 64 + tid], s0);
      s1 = fmaf(xv.y, s.W0[(k + 1) * 64 + tid], s1);
      s2 = fmaf(xv.z, s.W0[(k + 2) * 64 + tid], s2);
      s3 = fmaf(xv.w, s.W0[(k + 3) * 64 + tid], s3);
    }
    float4 uv = *reinterpret_cast<const float4*>(s.u);
    s0 = fmaf(uv.x, s.W0[12 * 64 + tid], s0);
    s1 = fmaf(uv.y, s.W0[13 * 64 + tid], s1);
    s2 = fmaf(uv.z, s.W0[14 * 64 + tid], s2);
    s3 = fmaf(uv.w, s.W0[15 * 64 + tid], s3);
    float sv[4] = {s0, s1, s2, s3};
    float a = xla_tanh(__fadd_rn(comb4(sv), s.b0[tid]));
    s.a1[tid] = a;
    s.om1[tid] = __fsub_rn(1.f, a);
  } else {
    int h = tid - 64;
    if (h < 36)
      *reinterpret_cast<float4*>(c + h * 4) = *reinterpret_cast<const float4*>(s.P + h * 4);
    else if (h < 39)
      *reinterpret_cast<float4*>(e + (h - 36) * 4) = *reinterpret_cast<const float4*>(s.x + (h - 36) * 4);
    else if (h < 48)
      pmo[h - 39] = s.zp[h - 39];
  }
  __syncthreads();
  // P2: D2 layer1 forward (W01) + T1 build (W23)
  if (tid < 64) {
    float d = dot4<64>(s.a1, s.W1, 64, tid);
    float a = xla_tanh(__fadd_rn(d, s.b1[tid]));
    s.a2[tid] = a;
    s.om2[tid] = __fsub_rn(1.f, a);
  } else {
    for (int idx = tid - 64; idx < 768; idx += 64) {
      int cc = idx & 63;
      s.Ta[idx] = tanh_jvp(s.W0[idx], s.a1[cc], s.om1[cc]);
    }
  }
  __syncthreads();
  // P3: T2 = jvp(T1 @ W1)
  mm12x64<true>(s.Ta, s.W1, s.a2, s.om2, s.Tb, tid);
  __syncthreads();
  // P4: layer2 forward (32 thr) + raw T3 (96 thr)
  if (tid < 32) {
    float d = dot4<64>(s.a2, s.W2, 32, tid);
    float a = xla_tanh(__fadd_rn(d, s.b2[tid]));
    s.a3[tid] = a;
    s.om3[tid] = __fsub_rn(1.f, a);
  } else {
    for (int idx = tid - 32; idx < 384; idx += 96) {
      int j = idx >> 5, cc = idx & 31;
      s.Ta[j * 32 + cc] = dot4<64>(s.Tb + j * 64, s.W2, 32, cc);
    }
  }
  __syncthreads();
  // P5: residual + xp (12 thr) + F (all 128)
  if (tid < 12) {
    const int i = tid;
    float d = dot4<32>(s.a3, s.W3, 12, i);
    float drift = 0.f;
    if (i < 3) drift = s.x[i + 3];
    else if (i >= 6 && i < 9) drift = s.x[i + 3];
    float base = fmaf(DT_STEP, drift, s.x[i]);
    s.xp[i] = __fadd_rn(base, __fadd_rn(d, s.b3[i]));
  }
  for (int idx = tid; idx < 144; idx += TPB) {
    int i = idx / 12, j = idx % 12;
    const float* tr = s.Ta + j * 32;
    float sv[4] = {0.f, 0.f, 0.f, 0.f};
#pragma unroll
    for (int k = 0; k < 32; k += 4) {
      float4 t4 = *reinterpret_cast<const float4*>(tr + k);
      float tv[4]; *reinterpret_cast<float4*>(tv) = t4;
#pragma unroll
      for (int l = 0; l < 4; ++l) {
        float t3 = tanh_jvp(tv[l], s.a3[k + l], s.om3[k + l]);
        sv[l] = fmaf(t3, s.W3[(k + l) * 12 + i], sv[l]);
      }
    }
    float acc = comb4(sv);
    float base = 0.f;
    if (i == j) base = 1.f;
    else if ((i < 3 || (i >= 6 && i < 9)) && j == i + 3) base = DT_STEP;
    s.F[idx] = __fadd_rn(acc, base);
  }
  __syncthreads();
}

// update: overlapped covariance-predict (W01: D6,D7,mT1) with measurement
// forward (W23: M1,M2), then the EKF update chain. FIRST skips D6/D7.
template<bool FIRST>
__device__ __forceinline__ void do_update(Smem& s, int tid) {
  if (tid < 64) {
    if (!FIRST) {
      // D6: FP = F @ P
      for (int idx = tid; idx < 144; idx += 64) {
        int i = idx / 12, j = idx % 12;
        float acc = 0.f;
#pragma unroll
        for (int k = 0; k < 12; ++k) acc = fmaf(s.F[i * 12 + k], s.P[k * 12 + j], acc);
        s.FP[idx] = acc;
      }
      barsync(1, 64);
      // D7: Pp = (FP @ F^T) + Q
      for (int idx = tid; idx < 144; idx += 64) {
        int i = idx / 12, j = idx % 12;
        float acc = 0.f;
#pragma unroll
        for (int k = 0; k < 12; ++k) acc = fmaf(s.FP[i * 12 + k], s.F[j * 12 + k], acc);
        s.Pp[idx] = __fadd_rn(acc, s.Qm[idx]);
      }
    }
    barsync(3, 128);   // wait for M1 (mg1) from W23
    // mT1 build
    for (int idx = tid; idx < 768; idx += 64) {
      int cc = idx & 63;
      s.Ta[idx] = s.mg1[cc] != 0.f ? s.mW0[idx] : 0.f;
    }
  } else {
    const int h = tid - 64;
    // M1: meas layer0 forward (relu), K=12 exact fp64
    {
      double acc = 0.;
#pragma unroll
      for (int k = 0; k < 12; ++k) acc = fma((double)s.xp[k], (double)s.mW0[k * 64 + h], acc);
      float pre = __fadd_rn((float)acc, s.mb0[h]);
      s.m1[h] = fmaxf(pre, 0.f);
      s.mg1[h] = pre > 0.f ? 1.f : 0.f;
    }
    bararrive(3, 128);
    barsync(2, 64);
    // M2: meas layer1 forward
    {
      float d = dot4<64>(s.m1, s.mW1, 64, h);
      float pre = __fadd_rn(d, s.mb1[h]);
      s.m2[h] = fmaxf(pre, 0.f);
      s.mg2[h] = pre > 0.f ? 1.f : 0.f;
    }
  }
  __syncthreads();
  // U1: mT2 = select(mT1 @ mW1)
  mm12x64<false>(s.Ta, s.mW1, s.m2, s.mg2, s.Tb, tid);
  __syncthreads();
  // U2: H (108 thr) + z_pred (9 thr)
  if (tid < 108) {
    int i = tid / 12, j = tid % 12;
    float f = dot4<64>(s.Tb + j * 64, s.mW2, 9, i);
    s.H[tid] = (i == j) ? __fadd_rn(f, 1.f) : f;
  } else if (tid < 117) {
    int i = tid - 108;
    float f = dot4<64>(s.m2, s.mW2, 9, i);
    s.zp[i] = __fadd_rn(s.xp[i], __fadd_rn(f, s.mb2[i]));
  }
  __syncthreads();
  // U3: HP = H @ Pp  and  PHt written directly into Mf columns 9..20
  for (int idx = tid; idx < 216; idx += TPB) {
    if (idx < 108) {
      int i = idx / 12, j = idx % 12;
      float acc = 0.f;
#pragma unroll
      for (int k = 0; k < 12; ++k) acc = fmaf(s.H[i * 12 + k], s.Pp[k * 12 + j], acc);
      s.HP[idx] = acc;
    } else {
      int r = idx - 108;
      int i = r / 9, j = r % 9;
      float acc = 0.f;
#pragma unroll
      for (int k = 0; k < 12; ++k) acc = fmaf(s.Pp[i * 12 + k], s.H[j * 12 + k], acc);
      s.Mf[j * 21 + 9 + i] = acc;
    }
  }
  __syncthreads();
  // U4: S = (HP @ H^T) + R into Mf columns 0..8
  if (tid < 81) {
    int i = tid / 9, cc = tid % 9;
    float acc = 0.f;
#pragma unroll
    for (int k = 0; k < 12; ++k) acc = fmaf(s.HP[i * 12 + k], s.H[cc * 12 + k], acc);
    s.Mf[i * 21 + cc] = __fadd_rn(acc, s.Rm[i * 9 + cc]);
  }
  __syncthreads();
  // LU solve (warp 0)
  if (tid < 32) lu_solve_warp(s.Mf, s.Kt, tid);
  __syncthreads();
  // U5: x_new = xp + K @ (z - zp);  E = I - K @ H
  if (tid < 12) {
    const int i = tid;
    float acc = 0.f;
#pragma unroll
    for (int k = 0; k < 9; ++k)
      acc = fmaf(s.Kt[k * 12 + i], __fsub_rn(s.z[k], s.zp[k]), acc);
    s.x[i] = __fadd_rn(s.xp[i], acc);
  }
  for (int idx = tid; idx < 144; idx += TPB) {
    int i = idx / 12, j = idx % 12;
    float acc = 0.f;
#pragma unroll
    for (int k = 0; k < 9; ++k)
      acc = fmaf(s.Kt[k * 12 + i], s.H[k * 12 + j], acc);
    s.FP[idx] = __fsub_rn((i == j) ? 1.f : 0.f, acc);
  }
  __syncthreads();
  // U6: P = E @ Pp   (no trailing sync; caller syncs after prefetch)
  for (int idx = tid; idx < 144; idx += TPB) {
    int i = idx / 12, j = idx % 12;
    float acc = 0.f;
#pragma unroll
    for (int k = 0; k < 12; ++k)
      acc = fmaf(s.FP[i * 12 + k], s.Pp[k * 12 + j], acc);
    s.P[idx] = acc;
  }
}

} // namespace

__global__ __launch_bounds__(TPB) void ekf_kernel(
    const float* __restrict__ controls,
    const float* __restrict__ measurements,
    const float* __restrict__ init_x,
    const float* __restrict__ init_P,
    const float* __restrict__ Qg,
    const float* __restrict__ Rg,
    const float* __restrict__ dW0, const float* __restrict__ db0,
    const float* __restrict__ dW1, const float* __restrict__ db1,
    const float* __restrict__ dW2, const float* __restrict__ db2,
    const float* __restrict__ dW3, const float* __restrict__ db3,
    const float* __restrict__ mW0p, const float* __restrict__ mb0p,
    const float* __restrict__ mW1p, const float* __restrict__ mb1p,
    const float* __restrict__ mW2p, const float* __restrict__ mb2p,
    float* __restrict__ out)
{
  extern __shared__ float smraw[];
  Smem& s = *reinterpret_cast<Smem*>(smraw);
  const int tid = threadIdx.x;
  const int b = blockIdx.x;

#define CPY(dst, src, n)  for (int i_ = tid; i_ < (n); i_ += TPB) (dst)[i_] = (src)[i_]
  CPY(s.W0, dW0, 1024); CPY(s.b0, db0, 64);
  CPY(s.W1, dW1, 4096); CPY(s.b1, db1, 64);
  CPY(s.W2, dW2, 2048); CPY(s.b2, db2, 32);
  CPY(s.W3, dW3, 384);  CPY(s.b3, db3, 12);
  CPY(s.mW0, mW0p, 768);  CPY(s.mb0, mb0p, 64);
  CPY(s.mW1, mW1p, 4096); CPY(s.mb1, mb1p, 64);
  CPY(s.mW2, mW2p, 576);  CPY(s.mb2, mb2p, 9);
  CPY(s.Qm, Qg, 144);
  CPY(s.Rm, Rg, 81);
#undef CPY
  if (tid < 12) s.xp[tid] = init_x[b * 12 + tid];
  for (int i = tid; i < 144; i += TPB) s.Pp[i] = init_P[b * 144 + i];
  if (tid >= 16 && tid < 25) s.z[tid - 16] = measurements[((size_t)b * NTIME + 0) * 9 + (tid - 16)];
  __syncthreads();

  float* est = out;
  float* pm  = out + (size_t)NBATCH * NTIME * 12;
  float* cv  = out + (size_t)NBATCH * NTIME * 21;

  // t = 0: measurement update only
  do_update<true>(s, tid);
  if (tid < 4) s.u[tid] = controls[((size_t)b * NTIME + 1) * 4 + tid];
  else if (tid >= 16 && tid < 25) s.z[tid - 16] = measurements[((size_t)b * NTIME + 1) * 9 + (tid - 16)];
  __syncthreads();

  for (int t = 1; t < NTIME; ++t) {
    size_t op = (size_t)b * NTIME + (t - 1);
    do_predict(s, tid, est + op * 12, pm + op * 9, cv + op * 144);
    do_update<false>(s, tid);
    if (t + 1 < NTIME) {
      if (tid < 4) s.u[tid] = controls[((size_t)b * NTIME + t + 1) * 4 + tid];
      else if (tid >= 16 && tid < 25) s.z[tid - 16] = measurements[((size_t)b * NTIME + t + 1) * 9 + (tid - 16)];
    }
    __syncthreads();
  }

  // final store for t = NTIME-1
  {
    size_t o = (size_t)b * NTIME + (NTIME - 1);
    if (tid < 12) est[o * 12 + tid] = s.x[tid];
    if (tid >= 32 && tid < 41) pm[o * 9 + (tid - 32)] = s.zp[tid - 32];
    for (int i = tid; i < 144; i += TPB) cv[o * 144 + i] = s.P[i];
  }
}

extern "C" void kernel_launch(void* const* d_in, const int* in_sizes, int n_in,
                              void* d_out, int out_size) {
  // inputs: 0 states (unused), 1 controls, 2 measurements, 3 initial_state,
  // 4 initial_covariance, 5 Q, 6 R, 7..14 dW/db 0..3, 15..20 mW/mb 0..2
  const float* controls = (const float*)d_in[1];
  const float* meas     = (const float*)d_in[2];
  const float* x0       = (const float*)d_in[3];
  const float* P0       = (const float*)d_in[4];
  const float* Qg       = (const float*)d_in[5];
  const float* Rg       = (const float*)d_in[6];
  const float* dW0 = (const float*)d_in[7];
  const float* db0 = (const float*)d_in[8];
  const float* dW1 = (const float*)d_in[9];
  const float* db1 = (const float*)d_in[10];
  const float* dW2 = (const float*)d_in[11];
  const float* db2 = (const float*)d_in[12];
  const float* dW3 = (const float*)d_in[13];
  const float* db3 = (const float*)d_in[14];
  const float* mW0 = (const float*)d_in[15];
  const float* mb0 = (const float*)d_in[16];
  const float* mW1 = (const float*)d_in[17];
  const float* mb1 = (const float*)d_in[18];
  const float* mW2 = (const float*)d_in[19];
  const float* mb2 = (const float*)d_in[20];
  float* out = (float*)d_out;

  int smem = (int)sizeof(Smem);
  cudaFuncSetAttribute(ekf_kernel, cudaFuncAttributeMaxDynamicSharedMemorySize, smem);
  ekf_kernel<<<NBATCH, TPB, smem>>>(controls, meas, x0, P0, Qg, Rg,
                                    dW0, db0, dW1, db1, dW2, db2, dW3, db3,
                                    mW0, mb0, mW1, mb1, mW2, mb2, out);
}

// round 13
// speedup vs baseline: 1.0025x; 1.0020x over previous
#include <cuda_runtime.h>

namespace {

constexpr int NBATCH = 256;
constexpr int NTIME  = 512;
constexpr int TPB    = 256;
constexpr float DT_STEP = 0.01f;

// XLA / Eigen f32 tanh rational approximation (bit-matches XLA's EmitTanh).
__device__ __forceinline__ float xla_tanh(float x) {
  const float CL = 7.90531110763549805f;
  float xc = fmaxf(fminf(x, CL), -CL);
  float x2 = __fmul_rn(xc, xc);
  float p = fmaf(x2, -2.76076847742355e-16f, 2.00018790482477e-13f);
  p = fmaf(x2, p, -8.60467152213735e-11f);
  p = fmaf(x2, p, 5.12229709037114e-08f);
  p = fmaf(x2, p, 1.48572235717979e-05f);
  p = fmaf(x2, p, 6.37261928875436e-04f);
  p = fmaf(x2, p, 4.89352455891786e-03f);
  p = __fmul_rn(xc, p);
  float q = fmaf(x2, 1.19825839466702e-06f, 1.18534705686654e-04f);
  q = fmaf(x2, q, 2.26843463243900e-03f);
  q = fmaf(x2, q, 4.89352518554385e-03f);
  float r = __fdiv_rn(p, q);
  return (fabsf(x) < 0.0004f) ? x : r;
}

// JAX tanh JVP (g + g*ans)*(1-ans), FFMA-contracted then FMUL.
__device__ __forceinline__ float tanh_jvp(float t, float a, float om) {
  return __fmul_rn(fmaf(t, a, t), om);
}

// NEON-style pairwise combine of 4 partial sums: (s0+s1)+(s2+s3)
__device__ __forceinline__ float comb4(const float* s) {
  return __fadd_rn(__fadd_rn(s[0], s[1]), __fadd_rn(s[2], s[3]));
}

__device__ __forceinline__ void barsync(int id, int cnt) {
  asm volatile("bar.sync %0, %1;" :: "r"(id), "r"(cnt) : "memory");
}
__device__ __forceinline__ void bararrive(int id, int cnt) {
  asm volatile("bar.arrive %0, %1;" :: "r"(id), "r"(cnt) : "memory");
}

// Full 4-lane interleaved dot (single thread), float4 a-loads.
template<int K>
__device__ __forceinline__ float dot4(const float* __restrict__ a,
                                      const float* __restrict__ w,
                                      int stride, int c) {
  float s0 = 0.f, s1 = 0.f, s2 = 0.f, s3 = 0.f;
#pragma unroll
  for (int k = 0; k < K; k += 4) {
    float4 av = *reinterpret_cast<const float4*>(a + k);
    s0 = fmaf(av.x, w[k * stride + c], s0);
    s1 = fmaf(av.y, w[(k + 1) * stride + c], s1);
    s2 = fmaf(av.z, w[(k + 2) * stride + c], s2);
    s3 = fmaf(av.w, w[(k + 3) * stride + c], s3);
  }
  float sv[4] = {s0, s1, s2, s3};
  return comb4(sv);
}

// Pair-split dot: thread pair (t, t^1); half h owns lanes 2h,2h+1.
// Reproduces comb4's (s0+s1)+(s2+s3) exactly via one shfl_xor.
template<int K>
__device__ __forceinline__ float dot4_pair(const float* __restrict__ a,
                                           const float* __restrict__ w,
                                           int stride, int c, int half) {
  float sA = 0.f, sB = 0.f;
  const int o = 2 * half;
#pragma unroll
  for (int k = 0; k < K; k += 4) {
    float2 av = *reinterpret_cast<const float2*>(a + k + o);
    sA = fmaf(av.x, w[(k + o) * stride + c], sA);
    sB = fmaf(av.y, w[(k + o + 1) * stride + c], sB);
  }
  float p = __fadd_rn(sA, sB);
  float po = __shfl_xor_sync(__activemask(), p, 1);
  return half == 0 ? __fadd_rn(p, po) : __fadd_rn(po, p);
}

struct Smem {
  float W0[1024]; float b0[64];
  float W1[4096]; float b1[64];
  float W2[2048]; float b2[32];
  float W3[384];  float b3[12];
  float mW0[768]; float mb0[64];
  float mW1[4096]; float mb1[64];
  float mW2[576]; float mb2[12];
  float Qm[144];  float Rm[84];
  float Ta[768], Tb[768];
  float a1[64], om1[64], a2[64], om2[64], a3[32], om3[32];
  float m1[64], mg1[64], m2[64], mg2[64];
  float x[12], xp[12], u[4], z[12], zp[12];
  float P[144], Pp[144], F[144], FP[144];
  float H[108], HP[108];
  float Mf[192];
  float Kt[108];
};

// O[12][64] = epilogue( A[12][64] @ W[64][64] ), 256 threads, 3 outputs each.
// c = tid&63 (column), jg = tid>>6 (row triple). Same FMA order per output.
template<bool TANH>
__device__ __forceinline__ void mm12x64(const float* __restrict__ A,
                                        const float* __restrict__ W,
                                        const float* __restrict__ act,
                                        const float* __restrict__ omk,
                                        float* __restrict__ O, int tid) {
  const int c = tid & 63;
  const int jg = tid >> 6;            // warp-uniform
  const float* a0 = A + (jg * 3 + 0) * 64;
  const float* a1p = A + (jg * 3 + 1) * 64;
  const float* a2p = A + (jg * 3 + 2) * 64;
  float acc[3][4];
#pragma unroll
  for (int o = 0; o < 3; ++o)
#pragma unroll
    for (int l = 0; l < 4; ++l) acc[o][l] = 0.f;
#pragma unroll 4
  for (int k = 0; k < 64; k += 4) {
    float A0[4], A1[4], A2[4];
    *reinterpret_cast<float4*>(A0) = *reinterpret_cast<const float4*>(a0 + k);
    *reinterpret_cast<float4*>(A1) = *reinterpret_cast<const float4*>(a1p + k);
    *reinterpret_cast<float4*>(A2) = *reinterpret_cast<const float4*>(a2p + k);
#pragma unroll
    for (int l = 0; l < 4; ++l) {
      float w = W[(k + l) * 64 + c];
      acc[0][l] = fmaf(A0[l], w, acc[0][l]);
      acc[1][l] = fmaf(A1[l], w, acc[1][l]);
      acc[2][l] = fmaf(A2[l], w, acc[2][l]);
    }
  }
  float f[3];
#pragma unroll
  for (int o = 0; o < 3; ++o) f[o] = comb4(acc[o]);
  if (TANH) {
    const float ax = act[c], ox = omk[c];
    O[(jg * 3 + 0) * 64 + c] = tanh_jvp(f[0], ax, ox);
    O[(jg * 3 + 1) * 64 + c] = tanh_jvp(f[1], ax, ox);
    O[(jg * 3 + 2) * 64 + c] = tanh_jvp(f[2], ax, ox);
  } else {
    const bool mx = omk[c] != 0.f;
    O[(jg * 3 + 0) * 64 + c] = mx ? f[0] : 0.f;
    O[(jg * 3 + 1) * 64 + c] = mx ? f[1] : 0.f;
    O[(jg * 3 + 2) * 64 + c] = mx ? f[2] : 0.f;
  }
}

// fp32 LAPACK sgetf2 + sgetrs on [S | PHt^T]. Warp 0 only.
__device__ __forceinline__ void lu_solve_warp(const float* __restrict__ Mf,
                                              float* __restrict__ Kt, int lane) {
  const unsigned FULL = 0xffffffffu;
  float r[21];
#pragma unroll
  for (int j = 0; j < 21; ++j) r[j] = (lane < 9) ? Mf[lane * 21 + j] : 0.f;
#pragma unroll
  for (int k = 0; k < 9; ++k) {
    float key = (lane >= k && lane < 9) ? fabsf(r[k]) : -1.0f;
    int idx = lane;
#pragma unroll
    for (int off = 8; off > 0; off >>= 1) {
      float ok = __shfl_xor_sync(FULL, key, off);
      int oi = __shfl_xor_sync(FULL, idx, off);
      if (ok > key || (ok == key && oi < idx)) { key = ok; idx = oi; }
    }
    int p = idx;
    int partner = (lane == k) ? p : ((lane == p) ? k : lane);
#pragma unroll
    for (int j = 0; j < 21; ++j) r[j] = __shfl_sync(FULL, r[j], partner);
    float piv = __shfl_sync(FULL, r[k], k);
    float rcp = __fdiv_rn(1.0f, piv);
    float rk[21];
#pragma unroll
    for (int j = 0; j < 21; ++j) rk[j] = __shfl_sync(FULL, r[j], k);
    if (lane > k && lane < 9) {
      float l = __fmul_rn(r[k], rcp);
      r[k] = l;
#pragma unroll
      for (int j = 0; j < 21; ++j)
        if (j > k) r[j] = fmaf(l, -rk[j], r[j]);
    }
  }
#pragma unroll
  for (int k = 8; k >= 0; --k) {
    if (lane == k) {
#pragma unroll
      for (int c = 9; c < 21; ++c) r[c] = __fdiv_rn(r[c], r[k]);
    }
#pragma unroll
    for (int c = 9; c < 21; ++c) {
      float xv = __shfl_sync(FULL, r[c], k);
      if (lane < k) r[c] = fmaf(r[k], -xv, r[c]);
    }
  }
  if (lane < 9) {
#pragma unroll
    for (int c = 0; c < 12; ++c) Kt[lane * 12 + c] = r[9 + c];
  }
}

// predict: consumes s.x, s.P, s.u -> produces s.xp, s.F.
// Phase 1 also stores the PREVIOUS step's outputs (e, pmo, c) on spare threads.
__device__ __forceinline__ void do_predict(Smem& s, int tid,
                                           float* __restrict__ e,
                                           float* __restrict__ pmo,
                                           float* __restrict__ c) {
  // P1: D1 forward pair-split (128 thr) | previous-step stores (128 thr)
  if (tid < 128) {
    const int col = tid >> 1, half = tid & 1, o = 2 * half;
    float sA = 0.f, sB = 0.f;
#pragma unroll
    for (int k = 0; k < 12; k += 4) {
      float2 xv = *reinterpret_cast<const float2*>(s.x + k + o);
      sA = fmaf(xv.x, s.W0[(k + o) * 64 + col], sA);
      sB = fmaf(xv.y, s.W0[(k + o + 1) * 64 + col], sB);
    }
    {
      float2 uv = *reinterpret_cast<const float2*>(s.u + o);
      sA = fmaf(uv.x, s.W0[(12 + o) * 64 + col], sA);
      sB = fmaf(uv.y, s.W0[(13 + o) * 64 + col], sB);
    }
    float p = __fadd_rn(sA, sB);
    float po = __shfl_xor_sync(0xffffffffu, p, 1);
    float d = half == 0 ? __fadd_rn(p, po) : __fadd_rn(po, p);
    if (half == 0) {
      float a = xla_tanh(__fadd_rn(d, s.b0[col]));
      s.a1[col] = a;
      s.om1[col] = __fsub_rn(1.f, a);
    }
  } else {
    int h = tid - 128;
    if (h < 36)
      *reinterpret_cast<float4*>(c + h * 4) = *reinterpret_cast<const float4*>(s.P + h * 4);
    else if (h < 39)
      *reinterpret_cast<float4*>(e + (h - 36) * 4) = *reinterpret_cast<const float4*>(s.x + (h - 36) * 4);
    else if (h < 48)
      pmo[h - 39] = s.zp[h - 39];
  }
  __syncthreads();
  // P2: D2 layer1 forward pair-split (128 thr) + T1 build (128 thr)
  if (tid < 128) {
    const int col = tid >> 1, half = tid & 1;
    float d = dot4_pair<64>(s.a1, s.W1, 64, col, half);
    if (half == 0) {
      float a = xla_tanh(__fadd_rn(d, s.b1[col]));
      s.a2[col] = a;
      s.om2[col] = __fsub_rn(1.f, a);
    }
  } else {
    for (int idx = tid - 128; idx < 768; idx += 128) {
      int cc = idx & 63;
      s.Ta[idx] = tanh_jvp(s.W0[idx], s.a1[cc], s.om1[cc]);
    }
  }
  __syncthreads();
  // P3: T2 = jvp(T1 @ W1)
  mm12x64<true>(s.Ta, s.W1, s.a2, s.om2, s.Tb, tid);
  __syncthreads();
  // P4: layer2 forward pair-split (64 thr) + raw T3 (192 thr, 2 dots each)
  if (tid < 64) {
    const int col = tid >> 1, half = tid & 1;
    float d = dot4_pair<64>(s.a2, s.W2, 32, col, half);
    if (half == 0) {
      float a = xla_tanh(__fadd_rn(d, s.b2[col]));
      s.a3[col] = a;
      s.om3[col] = __fsub_rn(1.f, a);
    }
  } else {
    int d0 = tid - 64;
#pragma unroll
    for (int r = 0; r < 2; ++r) {
      int dd = d0 + 192 * r;
      int j = dd >> 5, cc = dd & 31;
      s.Ta[j * 32 + cc] = dot4<64>(s.Tb + j * 64, s.W2, 32, cc);
    }
  }
  __syncthreads();
  // P5: F (144 thr) + xp (12 thr)
  if (tid < 144) {
    int i = tid / 12, j = tid % 12;
    const float* tr = s.Ta + j * 32;
    float sv[4] = {0.f, 0.f, 0.f, 0.f};
#pragma unroll
    for (int k = 0; k < 32; k += 4) {
      float tv[4];
      *reinterpret_cast<float4*>(tv) = *reinterpret_cast<const float4*>(tr + k);
#pragma unroll
      for (int l = 0; l < 4; ++l) {
        float t3 = tanh_jvp(tv[l], s.a3[k + l], s.om3[k + l]);
        sv[l] = fmaf(t3, s.W3[(k + l) * 12 + i], sv[l]);
      }
    }
    float acc = comb4(sv);
    float base = 0.f;
    if (i == j) base = 1.f;
    else if ((i < 3 || (i >= 6 && i < 9)) && j == i + 3) base = DT_STEP;
    s.F[tid] = __fadd_rn(acc, base);
  } else if (tid < 156) {
    const int i = tid - 144;
    float d = dot4<32>(s.a3, s.W3, 12, i);
    float drift = 0.f;
    if (i < 3) drift = s.x[i + 3];
    else if (i >= 6 && i < 9) drift = s.x[i + 3];
    float base = fmaf(DT_STEP, drift, s.x[i]);
    s.xp[i] = __fadd_rn(base, __fadd_rn(d, s.b3[i]));
  }
  __syncthreads();
}

// update: G1 (tid<128): D6,D7,mT1 | G2 (tid>=128): M1,M2. Then update chain.
template<bool FIRST>
__device__ __forceinline__ void do_update(Smem& s, int tid) {
  if (tid < 128) {
    if (!FIRST) {
      // D6: FP = F @ P
      for (int idx = tid; idx < 144; idx += 128) {
        int i = idx / 12, j = idx % 12;
        float acc = 0.f;
#pragma unroll
        for (int k = 0; k < 12; ++k) acc = fmaf(s.F[i * 12 + k], s.P[k * 12 + j], acc);
        s.FP[idx] = acc;
      }
      barsync(1, 128);
      // D7: Pp = (FP @ F^T) + Q
      for (int idx = tid; idx < 144; idx += 128) {
        int i = idx / 12, j = idx % 12;
        float acc = 0.f;
#pragma unroll
        for (int k = 0; k < 12; ++k) acc = fmaf(s.FP[i * 12 + k], s.F[j * 12 + k], acc);
        s.Pp[idx] = __fadd_rn(acc, s.Qm[idx]);
      }
    }
    barsync(3, 256);   // wait for M1 (mg1) from G2
    for (int idx = tid; idx < 768; idx += 128) {
      int cc = idx & 63;
      s.Ta[idx] = s.mg1[cc] != 0.f ? s.mW0[idx] : 0.f;
    }
  } else {
    const int h2 = tid - 128;
    if (h2 < 64) {
      // M1: meas layer0 forward (relu), K=12 exact fp64
      double acc = 0.;
#pragma unroll
      for (int k = 0; k < 12; ++k) acc = fma((double)s.xp[k], (double)s.mW0[k * 64 + h2], acc);
      float pre = __fadd_rn((float)acc, s.mb0[h2]);
      s.m1[h2] = fmaxf(pre, 0.f);
      s.mg1[h2] = pre > 0.f ? 1.f : 0.f;
    }
    bararrive(3, 256);
    barsync(2, 128);   // G2-internal: m1 ready
    // M2: meas layer1 forward pair-split (128 thr)
    {
      const int col = h2 >> 1, half = h2 & 1;
      float d = dot4_pair<64>(s.m1, s.mW1, 64, col, half);
      if (half == 0) {
        float pre = __fadd_rn(d, s.mb1[col]);
        s.m2[col] = fmaxf(pre, 0.f);
        s.mg2[col] = pre > 0.f ? 1.f : 0.f;
      }
    }
  }
  __syncthreads();
  // U1: mT2 = select(mT1 @ mW1)
  mm12x64<false>(s.Ta, s.mW1, s.m2, s.mg2, s.Tb, tid);
  __syncthreads();
  // U2: H pair-split (216 thr) + z_pred (tid 224..232)
  if (tid < 216) {
    int dd = tid >> 1, half = tid & 1;
    int i = dd / 12, j = dd % 12;
    float f = dot4_pair<64>(s.Tb + j * 64, s.mW2, 9, i, half);
    if (half == 0) s.H[dd] = (i == j) ? __fadd_rn(f, 1.f) : f;
  } else if (tid >= 224 && tid < 233) {
    int i = tid - 224;
    float f = dot4<64>(s.m2, s.mW2, 9, i);
    s.zp[i] = __fadd_rn(s.xp[i], __fadd_rn(f, s.mb2[i]));
  }
  __syncthreads();
  // U3: HP = H @ Pp (108) and PHt -> Mf cols 9..20 (108); single pass
  if (tid < 216) {
    if (tid < 108) {
      int i = tid / 12, j = tid % 12;
      float acc = 0.f;
#pragma unroll
      for (int k = 0; k < 12; ++k) acc = fmaf(s.H[i * 12 + k], s.Pp[k * 12 + j], acc);
      s.HP[tid] = acc;
    } else {
      int r = tid - 108;
      int i = r / 9, j = r % 9;
      float acc = 0.f;
#pragma unroll
      for (int k = 0; k < 12; ++k) acc = fmaf(s.Pp[i * 12 + k], s.H[j * 12 + k], acc);
      s.Mf[j * 21 + 9 + i] = acc;
    }
  }
  __syncthreads();
  // U4: S = (HP @ H^T) + R -> Mf cols 0..8
  if (tid < 81) {
    int i = tid / 9, cc = tid % 9;
    float acc = 0.f;
#pragma unroll
    for (int k = 0; k < 12; ++k) acc = fmaf(s.HP[i * 12 + k], s.H[cc * 12 + k], acc);
    s.Mf[i * 21 + cc] = __fadd_rn(acc, s.Rm[i * 9 + cc]);
  }
  __syncthreads();
  if (tid < 32) lu_solve_warp(s.Mf, s.Kt, tid);
  __syncthreads();
  // U5: E = I - K @ H (144 thr) + x_new (tid 144..155)
  if (tid < 144) {
    int i = tid / 12, j = tid % 12;
    float acc = 0.f;
#pragma unroll
    for (int k = 0; k < 9; ++k)
      acc = fmaf(s.Kt[k * 12 + i], s.H[k * 12 + j], acc);
    s.FP[tid] = __fsub_rn((i == j) ? 1.f : 0.f, acc);
  } else if (tid < 156) {
    const int i = tid - 144;
    float acc = 0.f;
#pragma unroll
    for (int k = 0; k < 9; ++k)
      acc = fmaf(s.Kt[k * 12 + i], __fsub_rn(s.z[k], s.zp[k]), acc);
    s.x[i] = __fadd_rn(s.xp[i], acc);
  }
  __syncthreads();
  // U6: P = E @ Pp (144 thr); no trailing sync (caller syncs)
  if (tid < 144) {
    int i = tid / 12, j = tid % 12;
    float acc = 0.f;
#pragma unroll
    for (int k = 0; k < 12; ++k)
      acc = fmaf(s.FP[i * 12 + k], s.Pp[k * 12 + j], acc);
    s.P[tid] = acc;
  }
}

} // namespace

__global__ __launch_bounds__(TPB, 2) void ekf_kernel(
    const float* __restrict__ controls,
    const float* __restrict__ measurements,
    const float* __restrict__ init_x,
    const float* __restrict__ init_P,
    const float* __restrict__ Qg,
    const float* __restrict__ Rg,
    const float* __restrict__ dW0, const float* __restrict__ db0,
    const float* __restrict__ dW1, const float* __restrict__ db1,
    const float* __restrict__ dW2, const float* __restrict__ db2,
    const float* __restrict__ dW3, const float* __restrict__ db3,
    const float* __restrict__ mW0p, const float* __restrict__ mb0p,
    const float* __restrict__ mW1p, const float* __restrict__ mb1p,
    const float* __restrict__ mW2p, const float* __restrict__ mb2p,
    float* __restrict__ out)
{
  extern __shared__ float smraw[];
  Smem& s = *reinterpret_cast<Smem*>(smraw);
  const int tid = threadIdx.x;
  const int b = blockIdx.x;

#define CPY(dst, src, n)  for (int i_ = tid; i_ < (n); i_ += TPB) (dst)[i_] = (src)[i_]
  CPY(s.W0, dW0, 1024); CPY(s.b0, db0, 64);
  CPY(s.W1, dW1, 4096); CPY(s.b1, db1, 64);
  CPY(s.W2, dW2, 2048); CPY(s.b2, db2, 32);
  CPY(s.W3, dW3, 384);  CPY(s.b3, db3, 12);
  CPY(s.mW0, mW0p, 768);  CPY(s.mb0, mb0p, 64);
  CPY(s.mW1, mW1p, 4096); CPY(s.mb1, mb1p, 64);
  CPY(s.mW2, mW2p, 576);  CPY(s.mb2, mb2p, 9);
  CPY(s.Qm, Qg, 144);
  CPY(s.Rm, Rg, 81);
#undef CPY
  if (tid < 12) s.xp[tid] = init_x[b * 12 + tid];
  if (tid >= 64 && tid < 208) s.Pp[tid - 64] = init_P[b * 144 + (tid - 64)];
  if (tid >= 16 && tid < 25) s.z[tid - 16] = measurements[((size_t)b * NTIME + 0) * 9 + (tid - 16)];
  __syncthreads();

  float* est = out;
  float* pm  = out + (size_t)NBATCH * NTIME * 12;
  float* cv  = out + (size_t)NBATCH * NTIME * 21;

  // t = 0: measurement update only
  do_update<true>(s, tid);
  if (tid >= 160 && tid < 164) s.u[tid - 160] = controls[((size_t)b * NTIME + 1) * 4 + (tid - 160)];
  else if (tid >= 176 && tid < 185) s.z[tid - 176] = measurements[((size_t)b * NTIME + 1) * 9 + (tid - 176)];
  __syncthreads();

  for (int t = 1; t < NTIME; ++t) {
    size_t op = (size_t)b * NTIME + (t - 1);
    do_predict(s, tid, est + op * 12, pm + op * 9, cv + op * 144);
    do_update<false>(s, tid);
    if (t + 1 < NTIME) {
      if (tid >= 160 && tid < 164) s.u[tid - 160] = controls[((size_t)b * NTIME + t + 1) * 4 + (tid - 160)];
      else if (tid >= 176 && tid < 185) s.z[tid - 176] = measurements[((size_t)b * NTIME + t + 1) * 9 + (tid - 176)];
    }
    __syncthreads();
  }

  // final store for t = NTIME-1
  {
    size_t o = (size_t)b * NTIME + (NTIME - 1);
    if (tid < 12) est[o * 12 + tid] = s.x[tid];
    if (tid >= 32 && tid < 41) pm[o * 9 + (tid - 32)] = s.zp[tid - 32];
    if (tid >= 64 && tid < 208) cv[o * 144 + (tid - 64)] = s.P[tid - 64];
  }
}

extern "C" void kernel_launch(void* const* d_in, const int* in_sizes, int n_in,
                              void* d_out, int out_size) {
  // inputs: 0 states (unused), 1 controls, 2 measurements, 3 initial_state,
  // 4 initial_covariance, 5 Q, 6 R, 7..14 dW/db 0..3, 15..20 mW/mb 0..2
  const float* controls = (const float*)d_in[1];
  const float* meas     = (const float*)d_in[2];
  const float* x0       = (const float*)d_in[3];
  const float* P0       = (const float*)d_in[4];
  const float* Qg       = (const float*)d_in[5];
  const float* Rg       = (const float*)d_in[6];
  const float* dW0 = (const float*)d_in[7];
  const float* db0 = (const float*)d_in[8];
  const float* dW1 = (const float*)d_in[9];
  const float* db1 = (const float*)d_in[10];
  const float* dW2 = (const float*)d_in[11];
  const float* db2 = (const float*)d_in[12];
  const float* dW3 = (const float*)d_in[13];
  const float* db3 = (const float*)d_in[14];
  const float* mW0 = (const float*)d_in[15];
  const float* mb0 = (const float*)d_in[16];
  const float* mW1 = (const float*)d_in[17];
  const float* mb1 = (const float*)d_in[18];
  const float* mW2 = (const float*)d_in[19];
  const float* mb2 = (const float*)d_in[20];
  float* out = (float*)d_out;

  int smem = (int)sizeof(Smem);
  cudaFuncSetAttribute(ekf_kernel, cudaFuncAttributeMaxDynamicSharedMemorySize, smem);
  ekf_kernel<<<NBATCH, TPB, smem>>>(controls, meas, x0, P0, Qg, Rg,
                                    dW0, db0, dW1, db1, dW2, db2, dW3, db3,
                                    mW0, mb0, mW1, mb1, mW2, mb2, out);
}

// round 15
// speedup vs baseline: 1.1587x; 1.1558x over previous
#include <cuda_runtime.h>

namespace {

constexpr int NBATCH = 256;
constexpr int NTIME  = 512;
constexpr int TPB    = 256;
constexpr float DT_STEP = 0.01f;

// XLA / Eigen f32 tanh rational approximation (bit-matches XLA's EmitTanh).
__device__ __forceinline__ float xla_tanh(float x) {
  const float CL = 7.90531110763549805f;
  float xc = fmaxf(fminf(x, CL), -CL);
  float x2 = __fmul_rn(xc, xc);
  float p = fmaf(x2, -2.76076847742355e-16f, 2.00018790482477e-13f);
  p = fmaf(x2, p, -8.60467152213735e-11f);
  p = fmaf(x2, p, 5.12229709037114e-08f);
  p = fmaf(x2, p, 1.48572235717979e-05f);
  p = fmaf(x2, p, 6.37261928875436e-04f);
  p = fmaf(x2, p, 4.89352455891786e-03f);
  p = __fmul_rn(xc, p);
  float q = fmaf(x2, 1.19825839466702e-06f, 1.18534705686654e-04f);
  q = fmaf(x2, q, 2.26843463243900e-03f);
  q = fmaf(x2, q, 4.89352518554385e-03f);
  float r = __fdiv_rn(p, q);
  return (fabsf(x) < 0.0004f) ? x : r;
}

// JAX tanh JVP (g + g*ans)*(1-ans), FFMA-contracted then FMUL.
__device__ __forceinline__ float tanh_jvp(float t, float a, float om) {
  return __fmul_rn(fmaf(t, a, t), om);
}

// NEON-style pairwise combine of 4 partial sums: (s0+s1)+(s2+s3)
__device__ __forceinline__ float comb4(const float* s) {
  return __fadd_rn(__fadd_rn(s[0], s[1]), __fadd_rn(s[2], s[3]));
}

__device__ __forceinline__ void barsync(int id, int cnt) {
  asm volatile("bar.sync %0, %1;" :: "r"(id), "r"(cnt) : "memory");
}
__device__ __forceinline__ void bararrive(int id, int cnt) {
  asm volatile("bar.arrive %0, %1;" :: "r"(id), "r"(cnt) : "memory");
}

// Full 4-lane interleaved dot (single thread), float4 a-loads.
template<int K>
__device__ __forceinline__ float dot4(const float* __restrict__ a,
                                      const float* __restrict__ w,
                                      int stride, int c) {
  float s0 = 0.f, s1 = 0.f, s2 = 0.f, s3 = 0.f;
#pragma unroll
  for (int k = 0; k < K; k += 4) {
    float4 av = *reinterpret_cast<const float4*>(a + k);
    s0 = fmaf(av.x, w[k * stride + c], s0);
    s1 = fmaf(av.y, w[(k + 1) * stride + c], s1);
    s2 = fmaf(av.z, w[(k + 2) * stride + c], s2);
    s3 = fmaf(av.w, w[(k + 3) * stride + c], s3);
  }
  float sv[4] = {s0, s1, s2, s3};
  return comb4(sv);
}

// Pair-split dot: thread pair (t, t^1); half h owns lanes 2h,2h+1.
// Reproduces comb4's (s0+s1)+(s2+s3) exactly via one shfl_xor.
template<int K>
__device__ __forceinline__ float dot4_pair(const float* __restrict__ a,
                                           const float* __restrict__ w,
                                           int stride, int c, int half) {
  float sA = 0.f, sB = 0.f;
  const int o = 2 * half;
#pragma unroll
  for (int k = 0; k < K; k += 4) {
    float2 av = *reinterpret_cast<const float2*>(a + k + o);
    sA = fmaf(av.x, w[(k + o) * stride + c], sA);
    sB = fmaf(av.y, w[(k + o + 1) * stride + c], sB);
  }
  float p = __fadd_rn(sA, sB);
  float po = __shfl_xor_sync(__activemask(), p, 1);
  return half == 0 ? __fadd_rn(p, po) : __fadd_rn(po, p);
}

// Sequential K=12 dot, rowA contiguous (48B-aligned) via float4, colB strided.
// FMA order identical to the scalar loop.
__device__ __forceinline__ float seqdot12_rv(const float* __restrict__ rowA,
                                             const float* __restrict__ colB,
                                             int strideB) {
  float a[12];
  *reinterpret_cast<float4*>(a)     = *reinterpret_cast<const float4*>(rowA);
  *reinterpret_cast<float4*>(a + 4) = *reinterpret_cast<const float4*>(rowA + 4);
  *reinterpret_cast<float4*>(a + 8) = *reinterpret_cast<const float4*>(rowA + 8);
  float acc = 0.f;
#pragma unroll
  for (int k = 0; k < 12; ++k) acc = fmaf(a[k], colB[k * strideB], acc);
  return acc;
}

// Sequential K=12 dot, both operands contiguous rows via float4.
__device__ __forceinline__ float seqdot12_rr(const float* __restrict__ rowA,
                                             const float* __restrict__ rowB) {
  float a[12], b[12];
  *reinterpret_cast<float4*>(a)     = *reinterpret_cast<const float4*>(rowA);
  *reinterpret_cast<float4*>(a + 4) = *reinterpret_cast<const float4*>(rowA + 4);
  *reinterpret_cast<float4*>(a + 8) = *reinterpret_cast<const float4*>(rowA + 8);
  *reinterpret_cast<float4*>(b)     = *reinterpret_cast<const float4*>(rowB);
  *reinterpret_cast<float4*>(b + 4) = *reinterpret_cast<const float4*>(rowB + 4);
  *reinterpret_cast<float4*>(b + 8) = *reinterpret_cast<const float4*>(rowB + 8);
  float acc = 0.f;
#pragma unroll
  for (int k = 0; k < 12; ++k) acc = fmaf(a[k], b[k], acc);
  return acc;
}

struct Smem {
  float W0[1024]; float b0[64];
  float W1[4096]; float b1[64];
  float W2[2048]; float b2[32];
  float W3[384];  float b3[12];
  float mW0[768]; float mb0[64];
  float mW1[4096]; float mb1[64];
  float mW2[576]; float mb2[12];
  float Qm[144];  float Rm[84];
  float Ta[768], Tb[768];
  float a1[64], om1[64], a2[64], om2[64], a3[32], om3[32];
  float m1[64], mg1[64], m2[64], mg2[64];
  float x[12], xp[12], u[4], z[12], zp[12];
  float P[144], Pp[144], F[144], FP[144];
  float H[108], HP[108];
  float Mf[192];
  float Kt[108];
};

// O[12][64] = epilogue( A[12][64] @ W[64][64] ), 256 threads, 3 outputs each.
template<bool TANH>
__device__ __forceinline__ void mm12x64(const float* __restrict__ A,
                                        const float* __restrict__ W,
                                        const float* __restrict__ act,
                                        const float* __restrict__ omk,
                                        float* __restrict__ O, int tid) {
  const int c = tid & 63;
  const int jg = tid >> 6;            // warp-uniform
  const float* a0 = A + (jg * 3 + 0) * 64;
  const float* a1p = A + (jg * 3 + 1) * 64;
  const float* a2p = A + (jg * 3 + 2) * 64;
  float acc[3][4];
#pragma unroll
  for (int o = 0; o < 3; ++o)
#pragma unroll
    for (int l = 0; l < 4; ++l) acc[o][l] = 0.f;
#pragma unroll 4
  for (int k = 0; k < 64; k += 4) {
    float A0[4], A1[4], A2[4];
    *reinterpret_cast<float4*>(A0) = *reinterpret_cast<const float4*>(a0 + k);
    *reinterpret_cast<float4*>(A1) = *reinterpret_cast<const float4*>(a1p + k);
    *reinterpret_cast<float4*>(A2) = *reinterpret_cast<const float4*>(a2p + k);
#pragma unroll
    for (int l = 0; l < 4; ++l) {
      float w = W[(k + l) * 64 + c];
      acc[0][l] = fmaf(A0[l], w, acc[0][l]);
      acc[1][l] = fmaf(A1[l], w, acc[1][l]);
      acc[2][l] = fmaf(A2[l], w, acc[2][l]);
    }
  }
  float f[3];
#pragma unroll
  for (int o = 0; o < 3; ++o) f[o] = comb4(acc[o]);
  if (TANH) {
    const float ax = act[c], ox = omk[c];
    O[(jg * 3 + 0) * 64 + c] = tanh_jvp(f[0], ax, ox);
    O[(jg * 3 + 1) * 64 + c] = tanh_jvp(f[1], ax, ox);
    O[(jg * 3 + 2) * 64 + c] = tanh_jvp(f[2], ax, ox);
  } else {
    const bool mx = omk[c] != 0.f;
    O[(jg * 3 + 0) * 64 + c] = mx ? f[0] : 0.f;
    O[(jg * 3 + 1) * 64 + c] = mx ? f[1] : 0.f;
    O[(jg * 3 + 2) * 64 + c] = mx ? f[2] : 0.f;
  }
}

// Column-parallel fp32 LAPACK sgetf2 + sgetrs on [S | PHt^T].
// Lane j owns column j (j = 0..20). Bit-identical ops/order to the
// row-parallel version: same l = A[i][k]*rcp products, same fmaf(l,-u,·)
// eliminations, same first-max pivot rule, same back-sub divisions.
__device__ __forceinline__ void lu_solve_warp(const float* __restrict__ Mf,
                                              float* __restrict__ Kt, int lane) {
  if (lane >= 21) return;
  const unsigned M21 = 0x001fffffu;
  float r[9];
#pragma unroll
  for (int i = 0; i < 9; ++i) r[i] = Mf[i * 21 + lane];
#pragma unroll
  for (int k = 0; k < 9; ++k) {
    // pivot: first-max scan of column k (lane k's registers), then broadcast
    int p = k;
    float best = fabsf(r[k]);
#pragma unroll
    for (int i = k + 1; i < 9; ++i) {
      float v = fabsf(r[i]);
      if (v > best) { best = v; p = i; }
    }
    p = __shfl_sync(M21, p, k);
    // swap rows k,p in every column (predicated register swap)
#pragma unroll
    for (int i = k + 1; i < 9; ++i)
      if (p == i) { float t = r[k]; r[k] = r[i]; r[i] = t; }
    float piv = __shfl_sync(M21, r[k], k);
    float rcp = __fdiv_rn(1.0f, piv);
#pragma unroll
    for (int i = k + 1; i < 9; ++i) {
      float tmp = __fmul_rn(r[i], rcp);       // correct on lane k
      float li = __shfl_sync(M21, tmp, k);
      if (lane == k) r[i] = li;               // store L multiplier in col k
      else if (lane > k) r[i] = fmaf(li, -r[k], r[i]);
    }
  }
  // back substitution (columns 9..20 are RHS)
#pragma unroll
  for (int k = 8; k >= 0; --k) {
    float ukk = __shfl_sync(M21, r[k], k);
    if (lane >= 9) r[k] = __fdiv_rn(r[k], ukk);
#pragma unroll
    for (int i = 0; i < k; ++i) {
      float uik = __shfl_sync(M21, r[i], k);
      if (lane >= 9) r[i] = fmaf(uik, -r[k], r[i]);
    }
  }
  if (lane >= 9) {
#pragma unroll
    for (int k = 0; k < 9; ++k) Kt[k * 12 + (lane - 9)] = r[k];
  }
}

// predict: consumes s.x, s.P, s.u -> produces s.xp, s.F.
// Phase 1 also stores the PREVIOUS step's outputs (e, pmo, c) on spare threads.
__device__ __forceinline__ void do_predict(Smem& s, int tid,
                                           float* __restrict__ e,
                                           float* __restrict__ pmo,
                                           float* __restrict__ c) {
  // P1: D1 forward pair-split (128 thr) | previous-step stores (128 thr)
  if (tid < 128) {
    const int col = tid >> 1, half = tid & 1, o = 2 * half;
    float sA = 0.f, sB = 0.f;
#pragma unroll
    for (int k = 0; k < 12; k += 4) {
      float2 xv = *reinterpret_cast<const float2*>(s.x + k + o);
      sA = fmaf(xv.x, s.W0[(k + o) * 64 + col], sA);
      sB = fmaf(xv.y, s.W0[(k + o + 1) * 64 + col], sB);
    }
    {
      float2 uv = *reinterpret_cast<const float2*>(s.u + o);
      sA = fmaf(uv.x, s.W0[(12 + o) * 64 + col], sA);
      sB = fmaf(uv.y, s.W0[(13 + o) * 64 + col], sB);
    }
    float p = __fadd_rn(sA, sB);
    float po = __shfl_xor_sync(0xffffffffu, p, 1);
    float d = half == 0 ? __fadd_rn(p, po) : __fadd_rn(po, p);
    if (half == 0) {
      float a = xla_tanh(__fadd_rn(d, s.b0[col]));
      s.a1[col] = a;
      s.om1[col] = __fsub_rn(1.f, a);
    }
  } else {
    int h = tid - 128;
    if (h < 36)
      *reinterpret_cast<float4*>(c + h * 4) = *reinterpret_cast<const float4*>(s.P + h * 4);
    else if (h < 39)
      *reinterpret_cast<float4*>(e + (h - 36) * 4) = *reinterpret_cast<const float4*>(s.x + (h - 36) * 4);
    else if (h < 48)
      pmo[h - 39] = s.zp[h - 39];
  }
  __syncthreads();
  // P2: D2 layer1 forward pair-split (128 thr) + T1 build (128 thr)
  if (tid < 128) {
    const int col = tid >> 1, half = tid & 1;
    float d = dot4_pair<64>(s.a1, s.W1, 64, col, half);
    if (half == 0) {
      float a = xla_tanh(__fadd_rn(d, s.b1[col]));
      s.a2[col] = a;
      s.om2[col] = __fsub_rn(1.f, a);
    }
  } else {
    for (int idx = tid - 128; idx < 768; idx += 128) {
      int cc = idx & 63;
      s.Ta[idx] = tanh_jvp(s.W0[idx], s.a1[cc], s.om1[cc]);
    }
  }
  __syncthreads();
  // P3: T2 = jvp(T1 @ W1)
  mm12x64<true>(s.Ta, s.W1, s.a2, s.om2, s.Tb, tid);
  __syncthreads();
  // P4: layer2 forward pair-split (64 thr) + raw T3 (192 thr, 2 dots each)
  if (tid < 64) {
    const int col = tid >> 1, half = tid & 1;
    float d = dot4_pair<64>(s.a2, s.W2, 32, col, half);
    if (half == 0) {
      float a = xla_tanh(__fadd_rn(d, s.b2[col]));
      s.a3[col] = a;
      s.om3[col] = __fsub_rn(1.f, a);
    }
  } else {
    int d0 = tid - 64;
#pragma unroll
    for (int r = 0; r < 2; ++r) {
      int dd = d0 + 192 * r;
      int j = dd >> 5, cc = dd & 31;
      s.Ta[j * 32 + cc] = dot4<64>(s.Tb + j * 64, s.W2, 32, cc);
    }
  }
  __syncthreads();
  // P5: F (144 thr) + xp (12 thr)
  if (tid < 144) {
    int i = tid / 12, j = tid % 12;
    const float* tr = s.Ta + j * 32;
    float sv[4] = {0.f, 0.f, 0.f, 0.f};
#pragma unroll
    for (int k = 0; k < 32; k += 4) {
      float tv[4];
      *reinterpret_cast<float4*>(tv) = *reinterpret_cast<const float4*>(tr + k);
#pragma unroll
      for (int l = 0; l < 4; ++l) {
        float t3 = tanh_jvp(tv[l], s.a3[k + l], s.om3[k + l]);
        sv[l] = fmaf(t3, s.W3[(k + l) * 12 + i], sv[l]);
      }
    }
    float acc = comb4(sv);
    float base = 0.f;
    if (i == j) base = 1.f;
    else if ((i < 3 || (i >= 6 && i < 9)) && j == i + 3) base = DT_STEP;
    s.F[tid] = __fadd_rn(acc, base);
  } else if (tid < 156) {
    const int i = tid - 144;
    float d = dot4<32>(s.a3, s.W3, 12, i);
    float drift = 0.f;
    if (i < 3) drift = s.x[i + 3];
    else if (i >= 6 && i < 9) drift = s.x[i + 3];
    float base = fmaf(DT_STEP, drift, s.x[i]);
    s.xp[i] = __fadd_rn(base, __fadd_rn(d, s.b3[i]));
  }
  __syncthreads();
}

// update: G1 (tid<128): D6,D7,mT1 | G2 (tid>=128): M1,M2. Then update chain.
template<bool FIRST>
__device__ __forceinline__ void do_update(Smem& s, int tid) {
  if (tid < 128) {
    if (!FIRST) {
      // D6: FP = F @ P  (F row via float4; order preserved)
      for (int idx = tid; idx < 144; idx += 128) {
        int i = idx / 12, j = idx % 12;
        s.FP[idx] = seqdot12_rv(s.F + i * 12, s.P + j, 12);
      }
      barsync(1, 128);
      // D7: Pp = (FP @ F^T) + Q  (both rows via float4)
      for (int idx = tid; idx < 144; idx += 128) {
        int i = idx / 12, j = idx % 12;
        float acc = seqdot12_rr(s.FP + i * 12, s.F + j * 12);
        s.Pp[idx] = __fadd_rn(acc, s.Qm[idx]);
      }
    }
    barsync(3, 256);   // wait for M1 (mg1) from G2
    for (int idx = tid; idx < 768; idx += 128) {
      int cc = idx & 63;
      s.Ta[idx] = s.mg1[cc] != 0.f ? s.mW0[idx] : 0.f;
    }
  } else {
    const int h2 = tid - 128;
    if (h2 < 64) {
      // M1: meas layer0 forward (relu), K=12 exact fp64
      double acc = 0.;
#pragma unroll
      for (int k = 0; k < 12; ++k) acc = fma((double)s.xp[k], (double)s.mW0[k * 64 + h2], acc);
      float pre = __fadd_rn((float)acc, s.mb0[h2]);
      s.m1[h2] = fmaxf(pre, 0.f);
      s.mg1[h2] = pre > 0.f ? 1.f : 0.f;
    }
    bararrive(3, 256);
    barsync(2, 128);   // G2-internal: m1 ready
    // M2: meas layer1 forward pair-split (128 thr)
    {
      const int col = h2 >> 1, half = h2 & 1;
      float d = dot4_pair<64>(s.m1, s.mW1, 64, col, half);
      if (half == 0) {
        float pre = __fadd_rn(d, s.mb1[col]);
        s.m2[col] = fmaxf(pre, 0.f);
        s.mg2[col] = pre > 0.f ? 1.f : 0.f;
      }
    }
  }
  __syncthreads();
  // U1: mT2 = select(mT1 @ mW1)
  mm12x64<false>(s.Ta, s.mW1, s.m2, s.mg2, s.Tb, tid);
  __syncthreads();
  // U2: H pair-split (216 thr) + z_pred (tid 224..232)
  if (tid < 216) {
    int dd = tid >> 1, half = tid & 1;
    int i = dd / 12, j = dd % 12;
    float f = dot4_pair<64>(s.Tb + j * 64, s.mW2, 9, i, half);
    if (half == 0) s.H[dd] = (i == j) ? __fadd_rn(f, 1.f) : f;
  } else if (tid >= 224 && tid < 233) {
    int i = tid - 224;
    float f = dot4<64>(s.m2, s.mW2, 9, i);
    s.zp[i] = __fadd_rn(s.xp[i], __fadd_rn(f, s.mb2[i]));
  }
  __syncthreads();
  // U3: HP = H @ Pp (108) and PHt -> Mf cols 9..20 (108); single pass
  if (tid < 216) {
    if (tid < 108) {
      int i = tid / 12, j = tid % 12;
      s.HP[tid] = seqdot12_rv(s.H + i * 12, s.Pp + j, 12);
    } else {
      int r = tid - 108;
      int i = r / 9, j = r % 9;
      s.Mf[j * 21 + 9 + i] = seqdot12_rr(s.Pp + i * 12, s.H + j * 12);
    }
  }
  __syncthreads();
  // U4: S = (HP @ H^T) + R -> Mf cols 0..8
  if (tid < 81) {
    int i = tid / 9, cc = tid % 9;
    float acc = seqdot12_rr(s.HP + i * 12, s.H + cc * 12);
    s.Mf[i * 21 + cc] = __fadd_rn(acc, s.Rm[i * 9 + cc]);
  }
  __syncthreads();
  if (tid < 32) lu_solve_warp(s.Mf, s.Kt, tid);
  __syncthreads();
  // U5: E = I - K @ H (144 thr) + x_new (tid 144..155)
  if (tid < 144) {
    int i = tid / 12, j = tid % 12;
    float acc = 0.f;
#pragma unroll
    for (int k = 0; k < 9; ++k)
      acc = fmaf(s.Kt[k * 12 + i], s.H[k * 12 + j], acc);
    s.FP[tid] = __fsub_rn((i == j) ? 1.f : 0.f, acc);
  } else if (tid < 156) {
    const int i = tid - 144;
    float acc = 0.f;
#pragma unroll
    for (int k = 0; k < 9; ++k)
      acc = fmaf(s.Kt[k * 12 + i], __fsub_rn(s.z[k], s.zp[k]), acc);
    s.x[i] = __fadd_rn(s.xp[i], acc);
  }
  __syncthreads();
  // U6: P = E @ Pp (144 thr); no trailing sync (caller syncs)
  if (tid < 144) {
    int i = tid / 12, j = tid % 12;
    s.P[tid] = seqdot12_rv(s.FP + i * 12, s.Pp + j, 12);
  }
}

} // namespace

__global__ __launch_bounds__(TPB, 2) void ekf_kernel(
    const float* __restrict__ controls,
    const float* __restrict__ measurements,
    const float* __restrict__ init_x,
    const float* __restrict__ init_P,
    const float* __restrict__ Qg,
    const float* __restrict__ Rg,
    const float* __restrict__ dW0, const float* __restrict__ db0,
    const float* __restrict__ dW1, const float* __restrict__ db1,
    const float* __restrict__ dW2, const float* __restrict__ db2,
    const float* __restrict__ dW3, const float* __restrict__ db3,
    const float* __restrict__ mW0p, const float* __restrict__ mb0p,
    const float* __restrict__ mW1p, const float* __restrict__ mb1p,
    const float* __restrict__ mW2p, const float* __restrict__ mb2p,
    float* __restrict__ out)
{
  extern __shared__ float smraw[];
  Smem& s = *reinterpret_cast<Smem*>(smraw);
  const int tid = threadIdx.x;
  const int b = blockIdx.x;

#define CPY(dst, src, n)  for (int i_ = tid; i_ < (n); i_ += TPB) (dst)[i_] = (src)[i_]
  CPY(s.W0, dW0, 1024); CPY(s.b0, db0, 64);
  CPY(s.W1, dW1, 4096); CPY(s.b1, db1, 64);
  CPY(s.W2, dW2, 2048); CPY(s.b2, db2, 32);
  CPY(s.W3, dW3, 384);  CPY(s.b3, db3, 12);
  CPY(s.mW0, mW0p, 768);  CPY(s.mb0, mb0p, 64);
  CPY(s.mW1, mW1p, 4096); CPY(s.mb1, mb1p, 64);
  CPY(s.mW2, mW2p, 576);  CPY(s.mb2, mb2p, 9);
  CPY(s.Qm, Qg, 144);
  CPY(s.Rm, Rg, 81);
#undef CPY
  if (tid < 12) s.xp[tid] = init_x[b * 12 + tid];
  if (tid >= 64 && tid < 208) s.Pp[tid - 64] = init_P[b * 144 + (tid - 64)];
  if (tid >= 16 && tid < 25) s.z[tid - 16] = measurements[((size_t)b * NTIME + 0) * 9 + (tid - 16)];
  __syncthreads();

  float* est = out;
  float* pm  = out + (size_t)NBATCH * NTIME * 12;
  float* cv  = out + (size_t)NBATCH * NTIME * 21;

  // t = 0: measurement update only
  do_update<true>(s, tid);
  if (tid >= 160 && tid < 164) s.u[tid - 160] = controls[((size_t)b * NTIME + 1) * 4 + (tid - 160)];
  else if (tid >= 176 && tid < 185) s.z[tid - 176] = measurements[((size_t)b * NTIME + 1) * 9 + (tid - 176)];
  __syncthreads();

  for (int t = 1; t < NTIME; ++t) {
    size_t op = (size_t)b * NTIME + (t - 1);
    do_predict(s, tid, est + op * 12, pm + op * 9, cv + op * 144);
    do_update<false>(s, tid);
    if (t + 1 < NTIME) {
      if (tid >= 160 && tid < 164) s.u[tid - 160] = controls[((size_t)b * NTIME + t + 1) * 4 + (tid - 160)];
      else if (tid >= 176 && tid < 185) s.z[tid - 176] = measurements[((size_t)b * NTIME + t + 1) * 9 + (tid - 176)];
    }
    __syncthreads();
  }

  // final store for t = NTIME-1
  {
    size_t o = (size_t)b * NTIME + (NTIME - 1);
    if (tid < 12) est[o * 12 + tid] = s.x[tid];
    if (tid >= 32 && tid < 41) pm[o * 9 + (tid - 32)] = s.zp[tid - 32];
    if (tid >= 64 && tid < 208) cv[o * 144 + (tid - 64)] = s.P[tid - 64];
  }
}

extern "C" void kernel_launch(void* const* d_in, const int* in_sizes, int n_in,
                              void* d_out, int out_size) {
  // inputs: 0 states (unused), 1 controls, 2 measurements, 3 initial_state,
  // 4 initial_covariance, 5 Q, 6 R, 7..14 dW/db 0..3, 15..20 mW/mb 0..2
  const float* controls = (const float*)d_in[1];
  const float* meas     = (const float*)d_in[2];
  const float* x0       = (const float*)d_in[3];
  const float* P0       = (const float*)d_in[4];
  const float* Qg       = (const float*)d_in[5];
  const float* Rg       = (const float*)d_in[6];
  const float* dW0 = (const float*)d_in[7];
  const float* db0 = (const float*)d_in[8];
  const float* dW1 = (const float*)d_in[9];
  const float* db1 = (const float*)d_in[10];
  const float* dW2 = (const float*)d_in[11];
  const float* db2 = (const float*)d_in[12];
  const float* dW3 = (const float*)d_in[13];
  const float* db3 = (const float*)d_in[14];
  const float* mW0 = (const float*)d_in[15];
  const float* mb0 = (const float*)d_in[16];
  const float* mW1 = (const float*)d_in[17];
  const float* mb1 = (const float*)d_in[18];
  const float* mW2 = (const float*)d_in[19];
  const float* mb2 = (const float*)d_in[20];
  float* out = (float*)d_out;

  int smem = (int)sizeof(Smem);
  cudaFuncSetAttribute(ekf_kernel, cudaFuncAttributeMaxDynamicSharedMemorySize, smem);
  ekf_kernel<<<NBATCH, TPB, smem>>>(controls, meas, x0, P0, Qg, Rg,
                                    dW0, db0, dW1, db1, dW2, db2, dW3, db3,
                                    mW0, mb0, mW1, mb1, mW2, mb2, out);
}